// round 3
// baseline (speedup 1.0000x reference)
#include <cuda_runtime.h>
#include <math.h>

#define NSC 128
#define NVC 64
#define TPCC 192
#define NNODES 16000
#define NEDGES 256000

#define INV_SQRT_NS 0.08838834764831845f
#define INV_SQRT_NV 0.125f
#define INV_SQRT_TPC 0.07216878364870323f
#define INV_SQRT3 0.5773502691896258f

typedef unsigned long long u64t;

// ---------------- scratch (static device globals; no runtime allocs) --------
__device__ float g_xs[NNODES * NSC];            // [n][128]
__device__ float g_xv[NNODES * 3 * NVC];        // [n][c][64]
__device__ float g_h[NEDGES * 128];             // [e][128]
__device__ float g_w[NEDGES * 384];             // [e][384]
__device__ float g_accs[NNODES * TPCC];         // [n][192]
__device__ float g_accv[NNODES * 3 * TPCC];     // [n][c][192]

// ---------------- helpers ----------------------------------------------------
__device__ __forceinline__ float silu_f(float x) {
    return x / (1.0f + __expf(-x));
}

__device__ __forceinline__ float4 f4mul(float4 a, float4 b) {
    return make_float4(a.x * b.x, a.y * b.y, a.z * b.z, a.w * b.w);
}
__device__ __forceinline__ float4 f4scale(float4 a, float s) {
    return make_float4(a.x * s, a.y * s, a.z * s, a.w * s);
}
__device__ __forceinline__ float4 f4fmas(float4 a, float s, float4 c) {
    return make_float4(fmaf(a.x, s, c.x), fmaf(a.y, s, c.y),
                       fmaf(a.z, s, c.z), fmaf(a.w, s, c.w));
}

// packed fp32x2 ops (Blackwell; ptxas never auto-emits these)
__device__ __forceinline__ u64t pack2(float x, float y) {
    u64t r; asm("mov.b64 %0, {%1, %2};" : "=l"(r) : "f"(x), "f"(y)); return r;
}
__device__ __forceinline__ void unpack2(u64t v, float& x, float& y) {
    asm("mov.b64 {%0, %1}, %2;" : "=f"(x), "=f"(y) : "l"(v));
}
__device__ __forceinline__ u64t fma2(u64t a, u64t b, u64t c) {
    u64t d;
    asm("fma.rn.f32x2 %0, %1, %2, %3;" : "=l"(d) : "l"(a), "l"(b), "l"(c));
    return d;
}

// vectorized global float4 reduction
__device__ __forceinline__ void red4(float* p, float4 v) {
    asm volatile("red.global.add.v4.f32 [%0], {%1, %2, %3, %4};"
                 :: "l"(p), "f"(v.x), "f"(v.y), "f"(v.z), "f"(v.w)
                 : "memory");
}

// ---------------- K1: node pre-mix ------------------------------------------
__global__ __launch_bounds__(320) void k_node_pre(
    const float* __restrict__ nf, const float* __restrict__ Ws,
    const float* __restrict__ bs, const float* __restrict__ Wv)
{
    __shared__ float sv[8][320];
    const int n0 = blockIdx.x * 8;
    const int tid = threadIdx.x;

    for (int idx = tid; idx < 8 * 320; idx += 320) {
        sv[idx / 320][idx % 320] = nf[(n0 + idx / 320) * 320 + idx % 320];
    }
    __syncthreads();

    if (tid < 128) {
        const int j = tid;
        float acc[8];
#pragma unroll
        for (int i = 0; i < 8; i++) acc[i] = 0.0f;
        for (int u = 0; u < 128; u++) {
            const float w = Ws[u * 128 + j];
#pragma unroll
            for (int i = 0; i < 8; i++) acc[i] = fmaf(sv[i][u], w, acc[i]);
        }
        const float b = bs[j];
#pragma unroll
        for (int i = 0; i < 8; i++)
            g_xs[(n0 + i) * 128 + j] = fmaf(acc[i], INV_SQRT_NS, b);
    } else {
        const int t = tid - 128;
        const int c = t / 64, vp = t % 64;
        float acc[8];
#pragma unroll
        for (int i = 0; i < 8; i++) acc[i] = 0.0f;
        for (int u = 0; u < 64; u++) {
            const float w = Wv[u * 64 + vp];
#pragma unroll
            for (int i = 0; i < 8; i++)
                acc[i] = fmaf(sv[i][128 + 3 * u + c], w, acc[i]);
        }
#pragma unroll
        for (int i = 0; i < 8; i++)
            g_xv[(n0 + i) * 192 + c * 64 + vp] = acc[i] * INV_SQRT_NV;
    }
}

// ---------------- K2: edge MLP layer 1  h = silu(ea @ W1 + b1) ---------------
__global__ __launch_bounds__(256) void k_edge_mlp1(
    const float* __restrict__ ea, const float* __restrict__ W1,
    const float* __restrict__ b1)
{
    __shared__ float W1s[16 * 128];
    __shared__ float b1s[128];
    __shared__ float eas[8][16];
    const int tid = threadIdx.x;
    const int e0 = blockIdx.x * 8;

    for (int idx = tid; idx < 2048; idx += 256) W1s[idx] = W1[idx];
    if (tid < 128) {
        b1s[tid] = b1[tid];
        eas[tid / 16][tid % 16] = ea[e0 * 16 + tid];
    }
    __syncthreads();

    const int i = tid >> 5;
    const int q = (tid & 31) * 4;
    float4 acc = *(const float4*)(b1s + q);
#pragma unroll
    for (int k = 0; k < 16; k++) {
        const float a = eas[i][k];
        const float4 w = *(const float4*)(W1s + k * 128 + q);
        acc = f4fmas(w, a, acc);
    }
    acc.x = silu_f(acc.x);
    acc.y = silu_f(acc.y);
    acc.z = silu_f(acc.z);
    acc.w = silu_f(acc.w);
    *(float4*)(g_h + (e0 + i) * 128 + q) = acc;
}

// ---------------- K3: edge MLP layer 2  w = h @ W2 + b2 (f32x2 packed) -------
// M=256000, N=384, K=128. BM=BN=128, BK=16, 256 threads, 8x8 register tiles,
// accumulators packed pairwise along N into fma.rn.f32x2.
// A is staged into smem pre-duplicated as (a,a) 64-bit pairs so the inner
// loop needs no pack instructions: 6x LDS.128 + 32x FMA2 per k.
__global__ __launch_bounds__(256, 2) void k_edge_mlp2(
    const float* __restrict__ W2, const float* __restrict__ b2)
{
    __shared__ u64t As2[16][128];   // [k][m] -> (a,a) duplicated pair
    __shared__ float Bs[16][128];   // [k][n]
    const int m0 = blockIdx.y * 128;
    const int n0 = blockIdx.x * 128;
    const int tid = threadIdx.x;
    const int tx = tid & 15;        // n-tile
    const int ty = tid >> 4;        // m-tile
    const int arow = tid >> 1;
    const int akq = (tid & 1) * 8;
    const int bk = tid >> 4;
    const int bn = (tid & 15) * 8;

    u64t acc2[8][4];                // acc2[i][p] = (acc[i][2p], acc[i][2p+1])
#pragma unroll
    for (int i = 0; i < 8; i++)
#pragma unroll
        for (int p = 0; p < 4; p++) acc2[i][p] = 0ull;

    // preload tile 0 into registers
    float4 a0 = *(const float4*)(g_h + (m0 + arow) * 128 + akq);
    float4 a1 = *(const float4*)(g_h + (m0 + arow) * 128 + akq + 4);
    float4 b0v = *(const float4*)(W2 + bk * 384 + n0 + bn);
    float4 b1v = *(const float4*)(W2 + bk * 384 + n0 + bn + 4);

    for (int kt = 0; kt < 8; kt++) {
        // stage registers -> smem (A duplicated into packed pairs)
        As2[akq + 0][arow] = pack2(a0.x, a0.x);
        As2[akq + 1][arow] = pack2(a0.y, a0.y);
        As2[akq + 2][arow] = pack2(a0.z, a0.z);
        As2[akq + 3][arow] = pack2(a0.w, a0.w);
        As2[akq + 4][arow] = pack2(a1.x, a1.x);
        As2[akq + 5][arow] = pack2(a1.y, a1.y);
        As2[akq + 6][arow] = pack2(a1.z, a1.z);
        As2[akq + 7][arow] = pack2(a1.w, a1.w);
        *(float4*)(&Bs[bk][bn]) = b0v;
        *(float4*)(&Bs[bk][bn + 4]) = b1v;
        __syncthreads();

        if (kt < 7) {   // prefetch next tile while computing
            const int k0n = (kt + 1) * 16;
            a0 = *(const float4*)(g_h + (m0 + arow) * 128 + k0n + akq);
            a1 = *(const float4*)(g_h + (m0 + arow) * 128 + k0n + akq + 4);
            b0v = *(const float4*)(W2 + (k0n + bk) * 384 + n0 + bn);
            b1v = *(const float4*)(W2 + (k0n + bk) * 384 + n0 + bn + 4);
        }

#pragma unroll
        for (int k = 0; k < 16; k++) {
            u64t a2[8];
#pragma unroll
            for (int i = 0; i < 8; i += 2) {
                const ulonglong2 t = *(const ulonglong2*)(&As2[k][ty * 8 + i]);
                a2[i] = t.x; a2[i + 1] = t.y;
            }
            u64t b2r[4];
            {
                const ulonglong2* bp = (const ulonglong2*)(&Bs[k][tx * 8]);
                const ulonglong2 t0 = bp[0];
                const ulonglong2 t1 = bp[1];
                b2r[0] = t0.x; b2r[1] = t0.y; b2r[2] = t1.x; b2r[3] = t1.y;
            }
#pragma unroll
            for (int i = 0; i < 8; i++)
#pragma unroll
                for (int p = 0; p < 4; p++)
                    acc2[i][p] = fma2(a2[i], b2r[p], acc2[i][p]);
        }
        __syncthreads();
    }

    const float4 bb0 = *(const float4*)(b2 + n0 + tx * 8);
    const float4 bb1 = *(const float4*)(b2 + n0 + tx * 8 + 4);
#pragma unroll
    for (int i = 0; i < 8; i++) {
        const int row = m0 + ty * 8 + i;
        float c0, c1, c2, c3, c4, c5, c6, c7;
        unpack2(acc2[i][0], c0, c1);
        unpack2(acc2[i][1], c2, c3);
        unpack2(acc2[i][2], c4, c5);
        unpack2(acc2[i][3], c6, c7);
        float4 o0 = make_float4(c0 + bb0.x, c1 + bb0.y, c2 + bb0.z, c3 + bb0.w);
        float4 o1 = make_float4(c4 + bb1.x, c5 + bb1.y, c6 + bb1.z, c7 + bb1.w);
        *(float4*)(g_w + row * 384 + n0 + tx * 8) = o0;
        *(float4*)(g_w + row * 384 + n0 + tx * 8 + 4) = o1;
    }
}

// ---------------- K4: edge messages + scatter-add ----------------------------
__global__ __launch_bounds__(256) void k_scatter(
    const int* __restrict__ eidx, const float* __restrict__ rsh)
{
    const int e = blockIdx.x * 8 + (threadIdx.x >> 5);
    const int lane = threadIdx.x & 31;
    const int dst = eidx[e];
    const int src = eidx[NEDGES + e];
    const float4 r = *(const float4*)(rsh + 4 * e);   // r0 = r.x, r1 = (y,z,w)

    const float* we = g_w + e * 384;
    const float* xs = g_xs + src * 128;
    const float* xv = g_xv + src * 192;
    float* as_ = g_accs + dst * 192;
    float* av = g_accv + dst * 576;

    {
        const int ch0 = lane * 4;
        const float4 wss = *(const float4*)(we + ch0);         // w_ss0
        const float4 wsv = *(const float4*)(we + 192 + ch0);   // w_sv1
        const float4 sj  = *(const float4*)(xs + ch0);
        red4(as_ + ch0, f4scale(f4mul(wss, sj), r.x));
        const float4 base = f4mul(wsv, sj);
        red4(av + ch0,        f4scale(base, r.y));
        red4(av + 192 + ch0,  f4scale(base, r.z));
        red4(av + 384 + ch0,  f4scale(base, r.w));
    }
    if (lane < 16) {
        const int u0 = lane * 4;
        const float4 wvv = *(const float4*)(we + 128 + u0);    // w_vv0
        const float4 wvs = *(const float4*)(we + 320 + u0);    // w_vs1
        const float4 v0 = *(const float4*)(xv + u0);
        const float4 v1 = *(const float4*)(xv + 64 + u0);
        const float4 v2 = *(const float4*)(xv + 128 + u0);
        float4 vd = f4scale(v0, r.y);
        vd = f4fmas(v1, r.z, vd);
        vd = f4fmas(v2, r.w, vd);
        red4(as_ + 128 + u0, f4scale(f4mul(wvv, vd), INV_SQRT3));
        const float4 wr = f4scale(wvs, r.x);
        red4(av + 128 + u0,        f4mul(wr, v0));
        red4(av + 192 + 128 + u0,  f4mul(wr, v1));
        red4(av + 384 + 128 + u0,  f4mul(wr, v2));
    }
}

// ---------------- K5: gating + node post-mix + residual ----------------------
__global__ __launch_bounds__(320) void k_node_post(
    const float* __restrict__ Wps, const float* __restrict__ Wpv,
    const float* __restrict__ xs_unused, float* __restrict__ out)
{
    __shared__ float gs[8][192];
    __shared__ float gv[8][3][192];
    const int n0 = blockIdx.x * 8;
    const int tid = threadIdx.x;

    for (int idx = tid; idx < 8 * 192; idx += 320) {
        const int i = idx / 192, u = idx % 192;
        const float a = g_accs[(n0 + i) * 192 + u];
        gs[i][u] = silu_f(a);
        const float v0 = g_accv[(n0 + i) * 576 + u];
        const float v1 = g_accv[(n0 + i) * 576 + 192 + u];
        const float v2 = g_accv[(n0 + i) * 576 + 384 + u];
        const float nrm = sqrtf(fmaf(v0, v0, fmaf(v1, v1, fmaf(v2, v2, 1e-12f))));
        const float sg = 1.0f / (1.0f + __expf(-nrm));
        gv[i][0][u] = v0 * sg;
        gv[i][1][u] = v1 * sg;
        gv[i][2][u] = v2 * sg;
    }
    __syncthreads();

    if (tid < 128) {
        const int j = tid;
        float acc[8];
#pragma unroll
        for (int i = 0; i < 8; i++) acc[i] = 0.0f;
        for (int u = 0; u < 192; u++) {
            const float w = Wps[u * 128 + j];
#pragma unroll
            for (int i = 0; i < 8; i++) acc[i] = fmaf(gs[i][u], w, acc[i]);
        }
#pragma unroll
        for (int i = 0; i < 8; i++)
            out[(n0 + i) * 320 + j] =
                g_xs[(n0 + i) * 128 + j] + acc[i] * INV_SQRT_TPC;
    } else {
        const int t = tid - 128;
        const int c = t / 64, vp = t % 64;
        float acc[8];
#pragma unroll
        for (int i = 0; i < 8; i++) acc[i] = 0.0f;
        for (int u = 0; u < 192; u++) {
            const float w = Wpv[u * 64 + vp];
#pragma unroll
            for (int i = 0; i < 8; i++) acc[i] = fmaf(gv[i][c][u], w, acc[i]);
        }
#pragma unroll
        for (int i = 0; i < 8; i++)
            out[(n0 + i) * 320 + 128 + vp * 3 + c] =
                g_xv[(n0 + i) * 192 + c * 64 + vp] + acc[i] * INV_SQRT_TPC;
    }
}

// ---------------- launcher ---------------------------------------------------
extern "C" void kernel_launch(void* const* d_in, const int* in_sizes, int n_in,
                              void* d_out, int out_size)
{
    (void)in_sizes; (void)n_in; (void)out_size;
    const float* nf   = (const float*)d_in[0];   // node_feat (16000, 320)
    const float* ea   = (const float*)d_in[1];   // edge_attr (256000, 16)
    const float* rsh  = (const float*)d_in[2];   // edge_rshs (256000, 4)
    const int*   eidx = (const int*)d_in[3];     // edge_index (2, 256000) int32
    const float* Wps  = (const float*)d_in[4];   // W_pre_s (128,128)
    const float* bps  = (const float*)d_in[5];   // b_pre_s (128,)
    const float* Wpv  = (const float*)d_in[6];   // W_pre_v (64,64)
    const float* W1   = (const float*)d_in[7];   // W1 (16,128)
    const float* b1   = (const float*)d_in[8];   // b1 (128,)
    const float* W2   = (const float*)d_in[9];   // W2 (128,384)
    const float* b2   = (const float*)d_in[10];  // b2 (384,)
    const float* Wposts = (const float*)d_in[11]; // W_post_s (192,128)
    const float* Wpostv = (const float*)d_in[12]; // W_post_v (192,64)
    float* out = (float*)d_out;

    void* accs_ptr = nullptr;
    void* accv_ptr = nullptr;
    cudaGetSymbolAddress(&accs_ptr, g_accs);
    cudaGetSymbolAddress(&accv_ptr, g_accv);
    cudaMemsetAsync(accs_ptr, 0, sizeof(float) * NNODES * TPCC);
    cudaMemsetAsync(accv_ptr, 0, sizeof(float) * NNODES * 3 * TPCC);

    k_node_pre<<<NNODES / 8, 320>>>(nf, Wps, bps, Wpv);
    k_edge_mlp1<<<NEDGES / 8, 256>>>(ea, W1, b1);
    k_edge_mlp2<<<dim3(3, NEDGES / 128), 256>>>(W2, b2);
    k_scatter<<<NEDGES / 8, 256>>>(eidx, rsh);
    k_node_post<<<NNODES / 8, 320>>>(Wposts, Wpostv, nullptr, out);
}

// round 5
// speedup vs baseline: 1.0723x; 1.0723x over previous
#include <cuda_runtime.h>
#include <math.h>

#define NSC 128
#define NVC 64
#define TPCC 192
#define NNODES 16000
#define NEDGES 256000

#define INV_SQRT_NS 0.08838834764831845f
#define INV_SQRT_NV 0.125f
#define INV_SQRT_TPC 0.07216878364870323f
#define INV_SQRT3 0.5773502691896258f

// ---------------- scratch (static device globals; no runtime allocs) --------
__device__ float g_xs[NNODES * NSC];            // [n][128]
__device__ float g_xv[NNODES * 3 * NVC];        // [n][c][64]
__device__ float g_h[NEDGES * 128];             // [e][128]
__device__ float g_accs[NNODES * TPCC];         // [n][192]
__device__ float g_accv[NNODES * 3 * TPCC];     // [n][c][192]

// ---------------- helpers ----------------------------------------------------
__device__ __forceinline__ float silu_f(float x) {
    return x / (1.0f + __expf(-x));
}

__device__ __forceinline__ float4 f4mul(float4 a, float4 b) {
    return make_float4(a.x * b.x, a.y * b.y, a.z * b.z, a.w * b.w);
}
__device__ __forceinline__ float4 f4scale(float4 a, float s) {
    return make_float4(a.x * s, a.y * s, a.z * s, a.w * s);
}
__device__ __forceinline__ float4 f4fmas(float4 a, float s, float4 c) {
    return make_float4(fmaf(a.x, s, c.x), fmaf(a.y, s, c.y),
                       fmaf(a.z, s, c.z), fmaf(a.w, s, c.w));
}

// vectorized global float4 reduction
__device__ __forceinline__ void red4(float* p, float4 v) {
    asm volatile("red.global.add.v4.f32 [%0], {%1, %2, %3, %4};"
                 :: "l"(p), "f"(v.x), "f"(v.y), "f"(v.z), "f"(v.w)
                 : "memory");
}

// ---------------- K1: node pre-mix ------------------------------------------
__global__ __launch_bounds__(320) void k_node_pre(
    const float* __restrict__ nf, const float* __restrict__ Ws,
    const float* __restrict__ bs, const float* __restrict__ Wv)
{
    __shared__ float sv[8][320];
    const int n0 = blockIdx.x * 8;
    const int tid = threadIdx.x;

    for (int idx = tid; idx < 8 * 320; idx += 320) {
        sv[idx / 320][idx % 320] = nf[(n0 + idx / 320) * 320 + idx % 320];
    }
    __syncthreads();

    if (tid < 128) {
        const int j = tid;
        float acc[8];
#pragma unroll
        for (int i = 0; i < 8; i++) acc[i] = 0.0f;
        for (int u = 0; u < 128; u++) {
            const float w = Ws[u * 128 + j];
#pragma unroll
            for (int i = 0; i < 8; i++) acc[i] = fmaf(sv[i][u], w, acc[i]);
        }
        const float b = bs[j];
#pragma unroll
        for (int i = 0; i < 8; i++)
            g_xs[(n0 + i) * 128 + j] = fmaf(acc[i], INV_SQRT_NS, b);
    } else {
        const int t = tid - 128;
        const int c = t / 64, vp = t % 64;
        float acc[8];
#pragma unroll
        for (int i = 0; i < 8; i++) acc[i] = 0.0f;
        for (int u = 0; u < 64; u++) {
            const float w = Wv[u * 64 + vp];
#pragma unroll
            for (int i = 0; i < 8; i++)
                acc[i] = fmaf(sv[i][128 + 3 * u + c], w, acc[i]);
        }
#pragma unroll
        for (int i = 0; i < 8; i++)
            g_xv[(n0 + i) * 192 + c * 64 + vp] = acc[i] * INV_SQRT_NV;
    }
}

// ---------------- K2: edge MLP layer 1  h = silu(ea @ W1 + b1) ---------------
__global__ __launch_bounds__(256) void k_edge_mlp1(
    const float* __restrict__ ea, const float* __restrict__ W1,
    const float* __restrict__ b1)
{
    __shared__ float W1s[16 * 128];
    __shared__ float b1s[128];
    __shared__ float eas[8][16];
    const int tid = threadIdx.x;
    const int e0 = blockIdx.x * 8;

    for (int idx = tid; idx < 2048; idx += 256) W1s[idx] = W1[idx];
    if (tid < 128) {
        b1s[tid] = b1[tid];
        eas[tid / 16][tid % 16] = ea[e0 * 16 + tid];
    }
    __syncthreads();

    const int i = tid >> 5;
    const int q = (tid & 31) * 4;
    float4 acc = *(const float4*)(b1s + q);
#pragma unroll
    for (int k = 0; k < 16; k++) {
        const float a = eas[i][k];
        const float4 w = *(const float4*)(W1s + k * 128 + q);
        acc = f4fmas(w, a, acc);
    }
    acc.x = silu_f(acc.x);
    acc.y = silu_f(acc.y);
    acc.z = silu_f(acc.z);
    acc.w = silu_f(acc.w);
    *(float4*)(g_h + (e0 + i) * 128 + q) = acc;
}

// ---------------- K3: fused  w = h @ W2 + b2  -> messages -> scatter ---------
// GEMM: M=256000, N=384 (3 chunks of 128 per blockIdx.x), K=128.
// BM=BN=128, BK=16, 256 threads, 8x8 register tiles (plain FFMA, as in R1).
// Epilogue: w tile staged to smem in two 64-edge passes, messages formed and
// reduced straight into g_accs / g_accv via red.global.add.v4.f32.
// Static smem: 8KB As + 8KB Bs + 32KB ws = 48KB exactly.
__global__ __launch_bounds__(256) void k_mlp2_scatter(
    const float* __restrict__ W2, const float* __restrict__ b2,
    const int* __restrict__ eidx, const float* __restrict__ rsh)
{
    __shared__ float As[16][128];   // [k][m]
    __shared__ float Bs[16][128];   // [k][n]
    __shared__ float ws[64][128];   // staged w tile (64 edges x 128 cols)

    const int chunk = blockIdx.x;        // 0,1,2 -> n0 = chunk*128
    const int m0 = blockIdx.y * 128;
    const int n0 = chunk * 128;
    const int tid = threadIdx.x;
    const int tx = tid & 15;        // n-tile
    const int ty = tid >> 4;        // m-tile
    const int arow = tid >> 1;
    const int akq = (tid & 1) * 8;
    const int bk = tid >> 4;
    const int bn = (tid & 15) * 8;
    const int warp = tid >> 5;
    const int lane = tid & 31;

    float acc[8][8];
#pragma unroll
    for (int i = 0; i < 8; i++)
#pragma unroll
        for (int j = 0; j < 8; j++) acc[i][j] = 0.0f;

    // preload tile 0 into registers
    float4 a0 = *(const float4*)(g_h + (m0 + arow) * 128 + akq);
    float4 a1 = *(const float4*)(g_h + (m0 + arow) * 128 + akq + 4);
    float4 b0v = *(const float4*)(W2 + bk * 384 + n0 + bn);
    float4 b1v = *(const float4*)(W2 + bk * 384 + n0 + bn + 4);

    for (int kt = 0; kt < 8; kt++) {
        As[akq + 0][arow] = a0.x; As[akq + 1][arow] = a0.y;
        As[akq + 2][arow] = a0.z; As[akq + 3][arow] = a0.w;
        As[akq + 4][arow] = a1.x; As[akq + 5][arow] = a1.y;
        As[akq + 6][arow] = a1.z; As[akq + 7][arow] = a1.w;
        *(float4*)(&Bs[bk][bn]) = b0v;
        *(float4*)(&Bs[bk][bn + 4]) = b1v;
        __syncthreads();

        if (kt < 7) {   // prefetch next tile while computing
            const int k0n = (kt + 1) * 16;
            a0 = *(const float4*)(g_h + (m0 + arow) * 128 + k0n + akq);
            a1 = *(const float4*)(g_h + (m0 + arow) * 128 + k0n + akq + 4);
            b0v = *(const float4*)(W2 + (k0n + bk) * 384 + n0 + bn);
            b1v = *(const float4*)(W2 + (k0n + bk) * 384 + n0 + bn + 4);
        }

#pragma unroll
        for (int k = 0; k < 16; k++) {
            float af[8], bf[8];
            *(float4*)(af) = *(const float4*)(&As[k][ty * 8]);
            *(float4*)(af + 4) = *(const float4*)(&As[k][ty * 8 + 4]);
            *(float4*)(bf) = *(const float4*)(&Bs[k][tx * 8]);
            *(float4*)(bf + 4) = *(const float4*)(&Bs[k][tx * 8 + 4]);
#pragma unroll
            for (int i = 0; i < 8; i++)
#pragma unroll
                for (int j = 0; j < 8; j++)
                    acc[i][j] = fmaf(af[i], bf[j], acc[i][j]);
        }
        __syncthreads();
    }

    const float4 bb0 = *(const float4*)(b2 + n0 + tx * 8);
    const float4 bb1 = *(const float4*)(b2 + n0 + tx * 8 + 4);

    // ---- epilogue: two passes of 64 edges each ----
    for (int pass = 0; pass < 2; pass++) {
        // threads owning rows [pass*64, pass*64+64) stage them (bias added)
        if ((ty >> 3) == pass) {
            const int rloc = (ty & 7) * 8;
#pragma unroll
            for (int i = 0; i < 8; i++) {
                float4 o0 = make_float4(acc[i][0] + bb0.x, acc[i][1] + bb0.y,
                                        acc[i][2] + bb0.z, acc[i][3] + bb0.w);
                float4 o1 = make_float4(acc[i][4] + bb1.x, acc[i][5] + bb1.y,
                                        acc[i][6] + bb1.z, acc[i][7] + bb1.w);
                *(float4*)(&ws[rloc + i][tx * 8]) = o0;
                *(float4*)(&ws[rloc + i][tx * 8 + 4]) = o1;
            }
        }
        __syncthreads();

        // scatter these 64 edges; one warp per edge, 8 edges per warp
        for (int t = warp; t < 64; t += 8) {
            const int e = m0 + pass * 64 + t;
            const int dst = eidx[e];
            const int src = eidx[NEDGES + e];
            const float4 r = *(const float4*)(rsh + 4 * e);
            const float* wrow = &ws[t][0];
            float* as_ = g_accs + dst * 192;
            float* av = g_accv + dst * 576;

            if (chunk == 0) {
                // cols 0..127 = w_ss0
                const int ch0 = lane * 4;
                const float4 wss = *(const float4*)(wrow + ch0);
                const float4 sj = *(const float4*)(g_xs + src * 128 + ch0);
                red4(as_ + ch0, f4scale(f4mul(wss, sj), r.x));
            } else if (chunk == 1) {
                if (lane < 16) {
                    // cols 128..191 = w_vv0[u], u = lane*4
                    const int u0 = lane * 4;
                    const float4 wvv = *(const float4*)(wrow + u0);
                    const float* xv = g_xv + src * 192;
                    const float4 v0 = *(const float4*)(xv + u0);
                    const float4 v1 = *(const float4*)(xv + 64 + u0);
                    const float4 v2 = *(const float4*)(xv + 128 + u0);
                    float4 vd = f4scale(v0, r.y);
                    vd = f4fmas(v1, r.z, vd);
                    vd = f4fmas(v2, r.w, vd);
                    red4(as_ + 128 + u0, f4scale(f4mul(wvv, vd), INV_SQRT3));
                } else {
                    // cols 192..255 = w_sv1[s], s = (lane-16)*4
                    const int s0 = (lane - 16) * 4;
                    const float4 wsv = *(const float4*)(wrow + 64 + s0);
                    const float4 sj = *(const float4*)(g_xs + src * 128 + s0);
                    const float4 base = f4mul(wsv, sj);
                    red4(av + s0,       f4scale(base, r.y));
                    red4(av + 192 + s0, f4scale(base, r.z));
                    red4(av + 384 + s0, f4scale(base, r.w));
                }
            } else {
                if (lane < 16) {
                    // cols 256..319 = w_sv1[s], s = 64 + lane*4
                    const int s0 = 64 + lane * 4;
                    const float4 wsv = *(const float4*)(wrow + lane * 4);
                    const float4 sj = *(const float4*)(g_xs + src * 128 + s0);
                    const float4 base = f4mul(wsv, sj);
                    red4(av + s0,       f4scale(base, r.y));
                    red4(av + 192 + s0, f4scale(base, r.z));
                    red4(av + 384 + s0, f4scale(base, r.w));
                } else {
                    // cols 320..383 = w_vs1[u], u = (lane-16)*4
                    const int u0 = (lane - 16) * 4;
                    const float4 wvs = *(const float4*)(wrow + 64 + u0);
                    const float* xv = g_xv + src * 192;
                    const float4 v0 = *(const float4*)(xv + u0);
                    const float4 v1 = *(const float4*)(xv + 64 + u0);
                    const float4 v2 = *(const float4*)(xv + 128 + u0);
                    const float4 wr = f4scale(wvs, r.x);
                    red4(av + 128 + u0,       f4mul(wr, v0));
                    red4(av + 192 + 128 + u0, f4mul(wr, v1));
                    red4(av + 384 + 128 + u0, f4mul(wr, v2));
                }
            }
        }
        __syncthreads();
    }
}

// ---------------- K5: gating + node post-mix + residual ----------------------
__global__ __launch_bounds__(320) void k_node_post(
    const float* __restrict__ Wps, const float* __restrict__ Wpv,
    float* __restrict__ out)
{
    __shared__ float gs[8][192];
    __shared__ float gv[8][3][192];
    const int n0 = blockIdx.x * 8;
    const int tid = threadIdx.x;

    for (int idx = tid; idx < 8 * 192; idx += 320) {
        const int i = idx / 192, u = idx % 192;
        const float a = g_accs[(n0 + i) * 192 + u];
        gs[i][u] = silu_f(a);
        const float v0 = g_accv[(n0 + i) * 576 + u];
        const float v1 = g_accv[(n0 + i) * 576 + 192 + u];
        const float v2 = g_accv[(n0 + i) * 576 + 384 + u];
        const float nrm = sqrtf(fmaf(v0, v0, fmaf(v1, v1, fmaf(v2, v2, 1e-12f))));
        const float sg = 1.0f / (1.0f + __expf(-nrm));
        gv[i][0][u] = v0 * sg;
        gv[i][1][u] = v1 * sg;
        gv[i][2][u] = v2 * sg;
    }
    __syncthreads();

    if (tid < 128) {
        const int j = tid;
        float acc[8];
#pragma unroll
        for (int i = 0; i < 8; i++) acc[i] = 0.0f;
        for (int u = 0; u < 192; u++) {
            const float w = Wps[u * 128 + j];
#pragma unroll
            for (int i = 0; i < 8; i++) acc[i] = fmaf(gs[i][u], w, acc[i]);
        }
#pragma unroll
        for (int i = 0; i < 8; i++)
            out[(n0 + i) * 320 + j] =
                g_xs[(n0 + i) * 128 + j] + acc[i] * INV_SQRT_TPC;
    } else {
        const int t = tid - 128;
        const int c = t / 64, vp = t % 64;
        float acc[8];
#pragma unroll
        for (int i = 0; i < 8; i++) acc[i] = 0.0f;
        for (int u = 0; u < 192; u++) {
            const float w = Wpv[u * 64 + vp];
#pragma unroll
            for (int i = 0; i < 8; i++) acc[i] = fmaf(gv[i][c][u], w, acc[i]);
        }
#pragma unroll
        for (int i = 0; i < 8; i++)
            out[(n0 + i) * 320 + 128 + vp * 3 + c] =
                g_xv[(n0 + i) * 192 + c * 64 + vp] + acc[i] * INV_SQRT_TPC;
    }
}

// ---------------- launcher ---------------------------------------------------
extern "C" void kernel_launch(void* const* d_in, const int* in_sizes, int n_in,
                              void* d_out, int out_size)
{
    (void)in_sizes; (void)n_in; (void)out_size;
    const float* nf   = (const float*)d_in[0];   // node_feat (16000, 320)
    const float* ea   = (const float*)d_in[1];   // edge_attr (256000, 16)
    const float* rsh  = (const float*)d_in[2];   // edge_rshs (256000, 4)
    const int*   eidx = (const int*)d_in[3];     // edge_index (2, 256000) int32
    const float* Wps  = (const float*)d_in[4];   // W_pre_s (128,128)
    const float* bps  = (const float*)d_in[5];   // b_pre_s (128,)
    const float* Wpv  = (const float*)d_in[6];   // W_pre_v (64,64)
    const float* W1   = (const float*)d_in[7];   // W1 (16,128)
    const float* b1   = (const float*)d_in[8];   // b1 (128,)
    const float* W2   = (const float*)d_in[9];   // W2 (128,384)
    const float* b2   = (const float*)d_in[10];  // b2 (384,)
    const float* Wposts = (const float*)d_in[11]; // W_post_s (192,128)
    const float* Wpostv = (const float*)d_in[12]; // W_post_v (192,64)
    float* out = (float*)d_out;

    void* accs_ptr = nullptr;
    void* accv_ptr = nullptr;
    cudaGetSymbolAddress(&accs_ptr, g_accs);
    cudaGetSymbolAddress(&accv_ptr, g_accv);
    cudaMemsetAsync(accs_ptr, 0, sizeof(float) * NNODES * TPCC);
    cudaMemsetAsync(accv_ptr, 0, sizeof(float) * NNODES * 3 * TPCC);

    k_node_pre<<<NNODES / 8, 320>>>(nf, Wps, bps, Wpv);
    k_edge_mlp1<<<NEDGES / 8, 256>>>(ea, W1, b1);
    k_mlp2_scatter<<<dim3(3, NEDGES / 128), 256>>>(W2, b2, eidx, rsh);
    k_node_post<<<NNODES / 8, 320>>>(Wposts, Wpostv, out);
}

// round 7
// speedup vs baseline: 1.3887x; 1.2950x over previous
#include <cuda_runtime.h>
#include <cuda_bf16.h>
#include <math.h>
#include <stdint.h>

#define NSC 128
#define NVC 64
#define TPCC 192
#define NNODES 16000
#define NEDGES 256000
#define NTILES 2000           // NEDGES / 128

#define INV_SQRT_NS 0.08838834764831845f
#define INV_SQRT_NV 0.125f
#define INV_SQRT_TPC 0.07216878364870323f
#define INV_SQRT3 0.5773502691896258f

// ---------------- scratch (static device globals; no runtime allocs) --------
__device__ float g_xs[NNODES * NSC];            // [n][128]
__device__ float g_xv[NNODES * 3 * NVC];        // [n][c][64]
__device__ float g_w[NEDGES * 384];             // [e][384]
__device__ float g_accs[NNODES * TPCC];         // [n][192]
__device__ float g_accv[NNODES * 3 * TPCC];     // [n][c][192]
// h split into bf16 hi/lo, row-major [e][128]
__device__ __nv_bfloat16 g_hhi[(size_t)NEDGES * 128];
__device__ __nv_bfloat16 g_hlo[(size_t)NEDGES * 128];
// W2 packed into mma.sync B fragments: [chunk][kstep][nfrag][lane] =
// uint4{ b0_hi, b1_hi, b0_lo, b1_lo }
__device__ uint4 g_Bpk[3 * 8 * 16 * 32];

// ---------------- generic helpers -------------------------------------------
__device__ __forceinline__ float silu_f(float x) {
    return x / (1.0f + __expf(-x));
}
__device__ __forceinline__ float4 f4mul(float4 a, float4 b) {
    return make_float4(a.x * b.x, a.y * b.y, a.z * b.z, a.w * b.w);
}
__device__ __forceinline__ float4 f4scale(float4 a, float s) {
    return make_float4(a.x * s, a.y * s, a.z * s, a.w * s);
}
__device__ __forceinline__ float4 f4fmas(float4 a, float s, float4 c) {
    return make_float4(fmaf(a.x, s, c.x), fmaf(a.y, s, c.y),
                       fmaf(a.z, s, c.z), fmaf(a.w, s, c.w));
}
__device__ __forceinline__ void red4(float* p, float4 v) {
    asm volatile("red.global.add.v4.f32 [%0], {%1, %2, %3, %4};"
                 :: "l"(p), "f"(v.x), "f"(v.y), "f"(v.z), "f"(v.w)
                 : "memory");
}
__device__ __forceinline__ unsigned short bf_bits(__nv_bfloat16 h) {
    return *(unsigned short*)&h;
}
// split fp32 into bf16 hi + bf16 lo (lo = bf16(x - hi))
__device__ __forceinline__ void bf_split(float x, unsigned short& hi,
                                         unsigned short& lo) {
    const __nv_bfloat16 h = __float2bfloat16(x);
    const __nv_bfloat16 l = __float2bfloat16(x - __bfloat162float(h));
    hi = bf_bits(h);
    lo = bf_bits(l);
}

// mma.sync m16n8k16 bf16, fp32 accum (sm_80+, works on plain sm_100 target)
__device__ __forceinline__ void mma_bf16(float c[4], const uint32_t a[4],
                                         uint32_t b0, uint32_t b1) {
    asm volatile(
        "mma.sync.aligned.m16n8k16.row.col.f32.bf16.bf16.f32 "
        "{%0,%1,%2,%3}, {%4,%5,%6,%7}, {%8,%9}, {%0,%1,%2,%3};"
        : "+f"(c[0]), "+f"(c[1]), "+f"(c[2]), "+f"(c[3])
        : "r"(a[0]), "r"(a[1]), "r"(a[2]), "r"(a[3]), "r"(b0), "r"(b1));
}

// ---------------- K1: node pre-mix ------------------------------------------
__global__ __launch_bounds__(320) void k_node_pre(
    const float* __restrict__ nf, const float* __restrict__ Ws,
    const float* __restrict__ bs, const float* __restrict__ Wv)
{
    __shared__ float sv[8][320];
    const int n0 = blockIdx.x * 8;
    const int tid = threadIdx.x;

    for (int idx = tid; idx < 8 * 320; idx += 320) {
        sv[idx / 320][idx % 320] = nf[(n0 + idx / 320) * 320 + idx % 320];
    }
    __syncthreads();

    if (tid < 128) {
        const int j = tid;
        float acc[8];
#pragma unroll
        for (int i = 0; i < 8; i++) acc[i] = 0.0f;
        for (int u = 0; u < 128; u++) {
            const float w = Ws[u * 128 + j];
#pragma unroll
            for (int i = 0; i < 8; i++) acc[i] = fmaf(sv[i][u], w, acc[i]);
        }
        const float b = bs[j];
#pragma unroll
        for (int i = 0; i < 8; i++)
            g_xs[(n0 + i) * 128 + j] = fmaf(acc[i], INV_SQRT_NS, b);
    } else {
        const int t = tid - 128;
        const int c = t / 64, vp = t % 64;
        float acc[8];
#pragma unroll
        for (int i = 0; i < 8; i++) acc[i] = 0.0f;
        for (int u = 0; u < 64; u++) {
            const float w = Wv[u * 64 + vp];
#pragma unroll
            for (int i = 0; i < 8; i++)
                acc[i] = fmaf(sv[i][128 + 3 * u + c], w, acc[i]);
        }
#pragma unroll
        for (int i = 0; i < 8; i++)
            g_xv[(n0 + i) * 192 + c * 64 + vp] = acc[i] * INV_SQRT_NV;
    }
}

// ---------------- prep: W2 -> packed B fragments -----------------------------
// index = ((chunk*8 + s)*16 + j)*32 + lane
// b0 holds W2[k0+tig*2][n], W2[k0+tig*2+1][n]  (k0 = 16*s, n = chunk*128+8*j+gid)
// b1 holds the same with k += 8. hi/lo split per element.
__global__ __launch_bounds__(256) void k_prep_b(const float* __restrict__ W2)
{
    const int idx = blockIdx.x * 256 + threadIdx.x;
    if (idx >= 3 * 8 * 16 * 32) return;
    const int lane = idx & 31;
    const int j = (idx >> 5) & 15;
    const int s = (idx >> 9) & 7;
    const int chunk = idx >> 12;

    const int gid = lane >> 2;
    const int tig = lane & 3;
    const int n = chunk * 128 + j * 8 + gid;
    const int k0 = s * 16 + tig * 2;

    unsigned short h0, l0, h1, l1, h2, l2, h3, l3;
    bf_split(W2[k0 * 384 + n],       h0, l0);
    bf_split(W2[(k0 + 1) * 384 + n], h1, l1);
    bf_split(W2[(k0 + 8) * 384 + n], h2, l2);
    bf_split(W2[(k0 + 9) * 384 + n], h3, l3);

    uint4 p;
    p.x = (uint32_t)h0 | ((uint32_t)h1 << 16);   // b0_hi
    p.y = (uint32_t)h2 | ((uint32_t)h3 << 16);   // b1_hi
    p.z = (uint32_t)l0 | ((uint32_t)l1 << 16);   // b0_lo
    p.w = (uint32_t)l2 | ((uint32_t)l3 << 16);   // b1_lo
    g_Bpk[idx] = p;
}

// ---------------- K2: edge MLP layer 1 -> h hi/lo bf16 -----------------------
__global__ __launch_bounds__(256) void k_edge_mlp1(
    const float* __restrict__ ea, const float* __restrict__ W1,
    const float* __restrict__ b1)
{
    __shared__ float W1s[16 * 128];
    __shared__ float b1s[128];
    __shared__ float eas[8][16];
    const int tid = threadIdx.x;
    const int e0 = blockIdx.x * 8;

    for (int idx = tid; idx < 2048; idx += 256) W1s[idx] = W1[idx];
    if (tid < 128) {
        b1s[tid] = b1[tid];
        eas[tid / 16][tid % 16] = ea[e0 * 16 + tid];
    }
    __syncthreads();

    const int i = tid >> 5;
    const int q = (tid & 31) * 4;
    float4 acc = *(const float4*)(b1s + q);
#pragma unroll
    for (int k = 0; k < 16; k++) {
        const float a = eas[i][k];
        const float4 w = *(const float4*)(W1s + k * 128 + q);
        acc = f4fmas(w, a, acc);
    }
    float v[4];
    v[0] = silu_f(acc.x); v[1] = silu_f(acc.y);
    v[2] = silu_f(acc.z); v[3] = silu_f(acc.w);

    unsigned short hb[4], lb[4];
#pragma unroll
    for (int j = 0; j < 4; j++) bf_split(v[j], hb[j], lb[j]);

    const size_t base = (size_t)(e0 + i) * 128 + q;
    uint2 ph, pl;
    ph.x = (uint32_t)hb[0] | ((uint32_t)hb[1] << 16);
    ph.y = (uint32_t)hb[2] | ((uint32_t)hb[3] << 16);
    pl.x = (uint32_t)lb[0] | ((uint32_t)lb[1] << 16);
    pl.y = (uint32_t)lb[2] | ((uint32_t)lb[3] << 16);
    *(uint2*)(g_hhi + base) = ph;
    *(uint2*)(g_hlo + base) = pl;
}

// ---------------- K3: tensor-core GEMM  w = h @ W2 + b2 (bf16x3) -------------
// 1 CTA = 128 edges x 384 cols. 8 warps, warp tile 16x128. 3 N-chunks.
// smem: A hi/lo padded (stride 136 bf16) + packed B chunk + bias.
#define SA_STRIDE 136
#define SMEM_A_BYTES (128 * SA_STRIDE * 2)          // 34816 per image
#define SMEM_B_OFF   (2 * SMEM_A_BYTES)             // 69632
#define SMEM_BIAS_OFF (SMEM_B_OFF + 65536)          // 135168
#define SMEM_MMA_BYTES (SMEM_BIAS_OFF + 1536)       // 136704
__global__ __launch_bounds__(256) void k_mlp2_mma(const float* __restrict__ b2)
{
    extern __shared__ unsigned char smem[];
    __nv_bfloat16* sAh = (__nv_bfloat16*)smem;
    __nv_bfloat16* sAl = (__nv_bfloat16*)(smem + SMEM_A_BYTES);
    uint4* sB = (uint4*)(smem + SMEM_B_OFF);
    float* sbias = (float*)(smem + SMEM_BIAS_OFF);

    const int tid = threadIdx.x;
    const int warp = tid >> 5;
    const int lane = tid & 31;
    const int tile = blockIdx.x;
    const int gid = lane >> 2;       // 0..7
    const int tig = lane & 3;        // 0..3
    const int row0 = warp * 16 + gid;

    // load A hi/lo (contiguous 32KB each) into padded smem
    {
        const uint2* ghh = (const uint2*)(g_hhi + (size_t)tile * 16384);
        const uint2* ghl = (const uint2*)(g_hlo + (size_t)tile * 16384);
        for (int i = tid; i < 4096; i += 256) {
            const int r = i >> 5, q = (i & 31) * 4;
            *(uint2*)&sAh[r * SA_STRIDE + q] = ghh[i];
            *(uint2*)&sAl[r * SA_STRIDE + q] = ghl[i];
        }
    }
    for (int i = tid; i < 384; i += 256) sbias[i] = b2[i];

    for (int chunk = 0; chunk < 3; chunk++) {
        __syncthreads();      // previous chunk done reading sB (or A just loaded)
        for (int i = tid; i < 4096; i += 256)
            sB[i] = g_Bpk[chunk * 4096 + i];
        __syncthreads();

        float c[16][4];
#pragma unroll
        for (int j = 0; j < 16; j++)
#pragma unroll
            for (int q = 0; q < 4; q++) c[j][q] = 0.0f;

#pragma unroll
        for (int s = 0; s < 8; s++) {
            const int kb = s * 16 + tig * 2;
            uint32_t ah[4], al[4];
            ah[0] = *(const uint32_t*)&sAh[row0 * SA_STRIDE + kb];
            ah[1] = *(const uint32_t*)&sAh[(row0 + 8) * SA_STRIDE + kb];
            ah[2] = *(const uint32_t*)&sAh[row0 * SA_STRIDE + kb + 8];
            ah[3] = *(const uint32_t*)&sAh[(row0 + 8) * SA_STRIDE + kb + 8];
            al[0] = *(const uint32_t*)&sAl[row0 * SA_STRIDE + kb];
            al[1] = *(const uint32_t*)&sAl[(row0 + 8) * SA_STRIDE + kb];
            al[2] = *(const uint32_t*)&sAl[row0 * SA_STRIDE + kb + 8];
            al[3] = *(const uint32_t*)&sAl[(row0 + 8) * SA_STRIDE + kb + 8];
#pragma unroll
            for (int j = 0; j < 16; j++) {
                const uint4 b = sB[(s * 16 + j) * 32 + lane];
                mma_bf16(c[j], ah, b.x, b.y);   // hi * hi
                mma_bf16(c[j], ah, b.z, b.w);   // hi * lo
                mma_bf16(c[j], al, b.x, b.y);   // lo * hi
            }
        }

        // epilogue: write this chunk's 128 cols with bias
        const int ebase = tile * 128;
#pragma unroll
        for (int j = 0; j < 16; j++) {
            const int col = chunk * 128 + j * 8 + tig * 2;
            const float bx = sbias[col], by = sbias[col + 1];
            float2 o0 = make_float2(c[j][0] + bx, c[j][1] + by);
            float2 o1 = make_float2(c[j][2] + bx, c[j][3] + by);
            *(float2*)&g_w[(size_t)(ebase + row0) * 384 + col] = o0;
            *(float2*)&g_w[(size_t)(ebase + row0 + 8) * 384 + col] = o1;
        }
    }
}

// ---------------- K4: edge messages + scatter-add ----------------------------
__global__ __launch_bounds__(256) void k_scatter(
    const int* __restrict__ eidx, const float* __restrict__ rsh)
{
    const int e = blockIdx.x * 8 + (threadIdx.x >> 5);
    const int lane = threadIdx.x & 31;
    const int dst = eidx[e];
    const int src = eidx[NEDGES + e];
    const float4 r = *(const float4*)(rsh + 4 * e);

    const float* we = g_w + (size_t)e * 384;
    const float* xs = g_xs + src * 128;
    const float* xv = g_xv + src * 192;
    float* as_ = g_accs + dst * 192;
    float* av = g_accv + dst * 576;

    {
        const int ch0 = lane * 4;
        const float4 wss = *(const float4*)(we + ch0);
        const float4 wsv = *(const float4*)(we + 192 + ch0);
        const float4 sj  = *(const float4*)(xs + ch0);
        red4(as_ + ch0, f4scale(f4mul(wss, sj), r.x));
        const float4 base = f4mul(wsv, sj);
        red4(av + ch0,        f4scale(base, r.y));
        red4(av + 192 + ch0,  f4scale(base, r.z));
        red4(av + 384 + ch0,  f4scale(base, r.w));
    }
    if (lane < 16) {
        const int u0 = lane * 4;
        const float4 wvv = *(const float4*)(we + 128 + u0);
        const float4 wvs = *(const float4*)(we + 320 + u0);
        const float4 v0 = *(const float4*)(xv + u0);
        const float4 v1 = *(const float4*)(xv + 64 + u0);
        const float4 v2 = *(const float4*)(xv + 128 + u0);
        float4 vd = f4scale(v0, r.y);
        vd = f4fmas(v1, r.z, vd);
        vd = f4fmas(v2, r.w, vd);
        red4(as_ + 128 + u0, f4scale(f4mul(wvv, vd), INV_SQRT3));
        const float4 wr = f4scale(wvs, r.x);
        red4(av + 128 + u0,        f4mul(wr, v0));
        red4(av + 192 + 128 + u0,  f4mul(wr, v1));
        red4(av + 384 + 128 + u0,  f4mul(wr, v2));
    }
}

// ---------------- K5: gating + node post-mix + residual ----------------------
__global__ __launch_bounds__(320) void k_node_post(
    const float* __restrict__ Wps, const float* __restrict__ Wpv,
    float* __restrict__ out)
{
    __shared__ float gs[8][192];
    __shared__ float gv[8][3][192];
    const int n0 = blockIdx.x * 8;
    const int tid = threadIdx.x;

    for (int idx = tid; idx < 8 * 192; idx += 320) {
        const int i = idx / 192, u = idx % 192;
        const float a = g_accs[(n0 + i) * 192 + u];
        gs[i][u] = silu_f(a);
        const float v0 = g_accv[(n0 + i) * 576 + u];
        const float v1 = g_accv[(n0 + i) * 576 + 192 + u];
        const float v2 = g_accv[(n0 + i) * 576 + 384 + u];
        const float nrm = sqrtf(fmaf(v0, v0, fmaf(v1, v1, fmaf(v2, v2, 1e-12f))));
        const float sg = 1.0f / (1.0f + __expf(-nrm));
        gv[i][0][u] = v0 * sg;
        gv[i][1][u] = v1 * sg;
        gv[i][2][u] = v2 * sg;
    }
    __syncthreads();

    if (tid < 128) {
        const int j = tid;
        float acc[8];
#pragma unroll
        for (int i = 0; i < 8; i++) acc[i] = 0.0f;
        for (int u = 0; u < 192; u++) {
            const float w = Wps[u * 128 + j];
#pragma unroll
            for (int i = 0; i < 8; i++) acc[i] = fmaf(gs[i][u], w, acc[i]);
        }
#pragma unroll
        for (int i = 0; i < 8; i++)
            out[(n0 + i) * 320 + j] =
                g_xs[(n0 + i) * 128 + j] + acc[i] * INV_SQRT_TPC;
    } else {
        const int t = tid - 128;
        const int c = t / 64, vp = t % 64;
        float acc[8];
#pragma unroll
        for (int i = 0; i < 8; i++) acc[i] = 0.0f;
        for (int u = 0; u < 192; u++) {
            const float w = Wpv[u * 64 + vp];
#pragma unroll
            for (int i = 0; i < 8; i++) acc[i] = fmaf(gv[i][c][u], w, acc[i]);
        }
#pragma unroll
        for (int i = 0; i < 8; i++)
            out[(n0 + i) * 320 + 128 + vp * 3 + c] =
                g_xv[(n0 + i) * 192 + c * 64 + vp] + acc[i] * INV_SQRT_TPC;
    }
}

// ---------------- launcher ---------------------------------------------------
extern "C" void kernel_launch(void* const* d_in, const int* in_sizes, int n_in,
                              void* d_out, int out_size)
{
    (void)in_sizes; (void)n_in; (void)out_size;
    const float* nf   = (const float*)d_in[0];
    const float* ea   = (const float*)d_in[1];
    const float* rsh  = (const float*)d_in[2];
    const int*   eidx = (const int*)d_in[3];
    const float* Wps  = (const float*)d_in[4];
    const float* bps  = (const float*)d_in[5];
    const float* Wpv  = (const float*)d_in[6];
    const float* W1   = (const float*)d_in[7];
    const float* b1   = (const float*)d_in[8];
    const float* W2   = (const float*)d_in[9];
    const float* b2   = (const float*)d_in[10];
    const float* Wposts = (const float*)d_in[11];
    const float* Wpostv = (const float*)d_in[12];
    float* out = (float*)d_out;

    cudaFuncSetAttribute(k_mlp2_mma,
                         cudaFuncAttributeMaxDynamicSharedMemorySize,
                         SMEM_MMA_BYTES);

    void* accs_ptr = nullptr;
    void* accv_ptr = nullptr;
    cudaGetSymbolAddress(&accs_ptr, g_accs);
    cudaGetSymbolAddress(&accv_ptr, g_accv);
    cudaMemsetAsync(accs_ptr, 0, sizeof(float) * NNODES * TPCC);
    cudaMemsetAsync(accv_ptr, 0, sizeof(float) * NNODES * 3 * TPCC);

    k_node_pre<<<NNODES / 8, 320>>>(nf, Wps, bps, Wpv);
    k_prep_b<<<48, 256>>>(W2);
    k_edge_mlp1<<<NEDGES / 8, 256>>>(ea, W1, b1);
    k_mlp2_mma<<<NTILES, 256, SMEM_MMA_BYTES>>>(b2);
    k_scatter<<<NEDGES / 8, 256>>>(eidx, rsh);
    k_node_post<<<NNODES / 8, 320>>>(Wposts, Wpostv, out);
}

// round 8
// speedup vs baseline: 1.6251x; 1.1703x over previous
#include <cuda_runtime.h>
#include <cuda_bf16.h>
#include <math.h>
#include <stdint.h>

#define NSC 128
#define NVC 64
#define TPCC 192
#define NNODES 16000
#define NEDGES 256000
#define NTILES 2000           // NEDGES / 128

#define INV_SQRT_NS 0.08838834764831845f
#define INV_SQRT_NV 0.125f
#define INV_SQRT_TPC 0.07216878364870323f
#define INV_SQRT3 0.5773502691896258f

// ---------------- scratch (static device globals; no runtime allocs) --------
__device__ float g_xs[NNODES * NSC];            // [n][128]
__device__ float g_xv[NNODES * 3 * NVC];        // [n][c][64]
__device__ float g_w[NEDGES * 384];             // [e][384]
__device__ float g_accs[NNODES * TPCC];         // [n][192]
__device__ float g_accv[NNODES * 3 * TPCC];     // [n][c][192]
// h split into bf16 hi/lo, row-major [e][128]
__device__ __nv_bfloat16 g_hhi[(size_t)NEDGES * 128];
__device__ __nv_bfloat16 g_hlo[(size_t)NEDGES * 128];
// W2 packed into mma.sync B fragments: [chunk][kstep][nfrag][lane] =
// uint4{ b0_hi, b1_hi, b0_lo, b1_lo }
__device__ uint4 g_Bpk[3 * 8 * 16 * 32];

// ---------------- generic helpers -------------------------------------------
__device__ __forceinline__ float silu_f(float x) {
    return x / (1.0f + __expf(-x));
}
__device__ __forceinline__ float4 f4mul(float4 a, float4 b) {
    return make_float4(a.x * b.x, a.y * b.y, a.z * b.z, a.w * b.w);
}
__device__ __forceinline__ float4 f4scale(float4 a, float s) {
    return make_float4(a.x * s, a.y * s, a.z * s, a.w * s);
}
__device__ __forceinline__ float4 f4fmas(float4 a, float s, float4 c) {
    return make_float4(fmaf(a.x, s, c.x), fmaf(a.y, s, c.y),
                       fmaf(a.z, s, c.z), fmaf(a.w, s, c.w));
}
__device__ __forceinline__ void red4(float* p, float4 v) {
    asm volatile("red.global.add.v4.f32 [%0], {%1, %2, %3, %4};"
                 :: "l"(p), "f"(v.x), "f"(v.y), "f"(v.z), "f"(v.w)
                 : "memory");
}
__device__ __forceinline__ unsigned short bf_bits(__nv_bfloat16 h) {
    return *(unsigned short*)&h;
}
// split fp32 into bf16 hi + bf16 lo (lo = bf16(x - hi))
__device__ __forceinline__ void bf_split(float x, unsigned short& hi,
                                         unsigned short& lo) {
    const __nv_bfloat16 h = __float2bfloat16(x);
    const __nv_bfloat16 l = __float2bfloat16(x - __bfloat162float(h));
    hi = bf_bits(h);
    lo = bf_bits(l);
}

// mma.sync m16n8k16 bf16, fp32 accum (sm_80+, works on plain sm_100 target)
__device__ __forceinline__ void mma_bf16(float c[4], const uint32_t a[4],
                                         uint32_t b0, uint32_t b1) {
    asm volatile(
        "mma.sync.aligned.m16n8k16.row.col.f32.bf16.bf16.f32 "
        "{%0,%1,%2,%3}, {%4,%5,%6,%7}, {%8,%9}, {%0,%1,%2,%3};"
        : "+f"(c[0]), "+f"(c[1]), "+f"(c[2]), "+f"(c[3])
        : "r"(a[0]), "r"(a[1]), "r"(a[2]), "r"(a[3]), "r"(b0), "r"(b1));
}

// ---------------- K1: node pre-mix ------------------------------------------
__global__ __launch_bounds__(320) void k_node_pre(
    const float* __restrict__ nf, const float* __restrict__ Ws,
    const float* __restrict__ bs, const float* __restrict__ Wv)
{
    __shared__ float sv[8][320];
    const int n0 = blockIdx.x * 8;
    const int tid = threadIdx.x;

    for (int idx = tid; idx < 8 * 320; idx += 320) {
        sv[idx / 320][idx % 320] = nf[(n0 + idx / 320) * 320 + idx % 320];
    }
    __syncthreads();

    if (tid < 128) {
        const int j = tid;
        float acc[8];
#pragma unroll
        for (int i = 0; i < 8; i++) acc[i] = 0.0f;
        for (int u = 0; u < 128; u++) {
            const float w = Ws[u * 128 + j];
#pragma unroll
            for (int i = 0; i < 8; i++) acc[i] = fmaf(sv[i][u], w, acc[i]);
        }
        const float b = bs[j];
#pragma unroll
        for (int i = 0; i < 8; i++)
            g_xs[(n0 + i) * 128 + j] = fmaf(acc[i], INV_SQRT_NS, b);
    } else {
        const int t = tid - 128;
        const int c = t / 64, vp = t % 64;
        float acc[8];
#pragma unroll
        for (int i = 0; i < 8; i++) acc[i] = 0.0f;
        for (int u = 0; u < 64; u++) {
            const float w = Wv[u * 64 + vp];
#pragma unroll
            for (int i = 0; i < 8; i++)
                acc[i] = fmaf(sv[i][128 + 3 * u + c], w, acc[i]);
        }
#pragma unroll
        for (int i = 0; i < 8; i++)
            g_xv[(n0 + i) * 192 + c * 64 + vp] = acc[i] * INV_SQRT_NV;
    }
}

// ---------------- prep: W2 -> packed B fragments -----------------------------
__global__ __launch_bounds__(256) void k_prep_b(const float* __restrict__ W2)
{
    const int idx = blockIdx.x * 256 + threadIdx.x;
    if (idx >= 3 * 8 * 16 * 32) return;
    const int lane = idx & 31;
    const int j = (idx >> 5) & 15;
    const int s = (idx >> 9) & 7;
    const int chunk = idx >> 12;

    const int gid = lane >> 2;
    const int tig = lane & 3;
    const int n = chunk * 128 + j * 8 + gid;
    const int k0 = s * 16 + tig * 2;

    unsigned short h0, l0, h1, l1, h2, l2, h3, l3;
    bf_split(W2[k0 * 384 + n],       h0, l0);
    bf_split(W2[(k0 + 1) * 384 + n], h1, l1);
    bf_split(W2[(k0 + 8) * 384 + n], h2, l2);
    bf_split(W2[(k0 + 9) * 384 + n], h3, l3);

    uint4 p;
    p.x = (uint32_t)h0 | ((uint32_t)h1 << 16);   // b0_hi
    p.y = (uint32_t)h2 | ((uint32_t)h3 << 16);   // b1_hi
    p.z = (uint32_t)l0 | ((uint32_t)l1 << 16);   // b0_lo
    p.w = (uint32_t)l2 | ((uint32_t)l3 << 16);   // b1_lo
    g_Bpk[idx] = p;
}

// ---------------- K2: edge MLP layer 1 -> h hi/lo bf16 -----------------------
__global__ __launch_bounds__(256) void k_edge_mlp1(
    const float* __restrict__ ea, const float* __restrict__ W1,
    const float* __restrict__ b1)
{
    __shared__ float W1s[16 * 128];
    __shared__ float b1s[128];
    __shared__ float eas[8][16];
    const int tid = threadIdx.x;
    const int e0 = blockIdx.x * 8;

    for (int idx = tid; idx < 2048; idx += 256) W1s[idx] = W1[idx];
    if (tid < 128) {
        b1s[tid] = b1[tid];
        eas[tid / 16][tid % 16] = ea[e0 * 16 + tid];
    }
    __syncthreads();

    const int i = tid >> 5;
    const int q = (tid & 31) * 4;
    float4 acc = *(const float4*)(b1s + q);
#pragma unroll
    for (int k = 0; k < 16; k++) {
        const float a = eas[i][k];
        const float4 w = *(const float4*)(W1s + k * 128 + q);
        acc = f4fmas(w, a, acc);
    }
    float v[4];
    v[0] = silu_f(acc.x); v[1] = silu_f(acc.y);
    v[2] = silu_f(acc.z); v[3] = silu_f(acc.w);

    unsigned short hb[4], lb[4];
#pragma unroll
    for (int j = 0; j < 4; j++) bf_split(v[j], hb[j], lb[j]);

    const size_t base = (size_t)(e0 + i) * 128 + q;
    uint2 ph, pl;
    ph.x = (uint32_t)hb[0] | ((uint32_t)hb[1] << 16);
    ph.y = (uint32_t)hb[2] | ((uint32_t)hb[3] << 16);
    pl.x = (uint32_t)lb[0] | ((uint32_t)lb[1] << 16);
    pl.y = (uint32_t)lb[2] | ((uint32_t)lb[3] << 16);
    *(uint2*)(g_hhi + base) = ph;
    *(uint2*)(g_hlo + base) = pl;
}

// ---------------- K3: tensor-core GEMM  w = h @ W2 + b2 (bf16x3) -------------
// 1 CTA = 128 edges x 384 cols. 8 warps, warp tile 16 x (64 per half).
// B staged in 32KB halves (8 n-frags) -> smem ~104KB -> 2 CTAs/SM.
#define SA_STRIDE 136
#define SMEM_A_BYTES (128 * SA_STRIDE * 2)          // 34816 per image
#define SMEM_B_OFF   (2 * SMEM_A_BYTES)             // 69632
#define SMEM_BIAS_OFF (SMEM_B_OFF + 32768)          // 102400
#define SMEM_MMA_BYTES (SMEM_BIAS_OFF + 1536)       // 103936
__global__ __launch_bounds__(256) void k_mlp2_mma(const float* __restrict__ b2)
{
    extern __shared__ unsigned char smem[];
    __nv_bfloat16* sAh = (__nv_bfloat16*)smem;
    __nv_bfloat16* sAl = (__nv_bfloat16*)(smem + SMEM_A_BYTES);
    uint4* sB = (uint4*)(smem + SMEM_B_OFF);        // 2048 uint4 = 32KB
    float* sbias = (float*)(smem + SMEM_BIAS_OFF);

    const int tid = threadIdx.x;
    const int warp = tid >> 5;
    const int lane = tid & 31;
    const int tile = blockIdx.x;
    const int gid = lane >> 2;       // 0..7
    const int tig = lane & 3;        // 0..3
    const int row0 = warp * 16 + gid;

    // load A hi/lo (contiguous 32KB each) into padded smem
    {
        const uint2* ghh = (const uint2*)(g_hhi + (size_t)tile * 16384);
        const uint2* ghl = (const uint2*)(g_hlo + (size_t)tile * 16384);
        for (int i = tid; i < 4096; i += 256) {
            const int r = i >> 5, q = (i & 31) * 4;
            *(uint2*)&sAh[r * SA_STRIDE + q] = ghh[i];
            *(uint2*)&sAl[r * SA_STRIDE + q] = ghl[i];
        }
    }
    for (int i = tid; i < 384; i += 256) sbias[i] = b2[i];

    const int ebase = tile * 128;

    for (int cs = 0; cs < 6; cs++) {            // (chunk, half)
        const int chunk = cs >> 1;
        const int half = cs & 1;

        __syncthreads();    // previous stage done reading sB (or A just loaded)
        for (int i = tid; i < 2048; i += 256) {
            const int s = i >> 8, jj = (i >> 5) & 7, ln = i & 31;
            sB[i] = g_Bpk[(((chunk * 8 + s) * 16) + half * 8 + jj) * 32 + ln];
        }
        __syncthreads();

        float c[8][4];
#pragma unroll
        for (int j = 0; j < 8; j++)
#pragma unroll
            for (int q = 0; q < 4; q++) c[j][q] = 0.0f;

#pragma unroll
        for (int s = 0; s < 8; s++) {
            const int kb = s * 16 + tig * 2;
            uint32_t ah[4], al[4];
            ah[0] = *(const uint32_t*)&sAh[row0 * SA_STRIDE + kb];
            ah[1] = *(const uint32_t*)&sAh[(row0 + 8) * SA_STRIDE + kb];
            ah[2] = *(const uint32_t*)&sAh[row0 * SA_STRIDE + kb + 8];
            ah[3] = *(const uint32_t*)&sAh[(row0 + 8) * SA_STRIDE + kb + 8];
            al[0] = *(const uint32_t*)&sAl[row0 * SA_STRIDE + kb];
            al[1] = *(const uint32_t*)&sAl[(row0 + 8) * SA_STRIDE + kb];
            al[2] = *(const uint32_t*)&sAl[row0 * SA_STRIDE + kb + 8];
            al[3] = *(const uint32_t*)&sAl[(row0 + 8) * SA_STRIDE + kb + 8];
#pragma unroll
            for (int j = 0; j < 8; j++) {
                const uint4 b = sB[(s * 8 + j) * 32 + lane];
                mma_bf16(c[j], ah, b.x, b.y);   // hi * hi
                mma_bf16(c[j], ah, b.z, b.w);   // hi * lo
                mma_bf16(c[j], al, b.x, b.y);   // lo * hi
            }
        }

        // epilogue: write this stage's 64 cols with bias
#pragma unroll
        for (int j = 0; j < 8; j++) {
            const int col = chunk * 128 + half * 64 + j * 8 + tig * 2;
            const float bx = sbias[col], by = sbias[col + 1];
            float2 o0 = make_float2(c[j][0] + bx, c[j][1] + by);
            float2 o1 = make_float2(c[j][2] + bx, c[j][3] + by);
            *(float2*)&g_w[(size_t)(ebase + row0) * 384 + col] = o0;
            *(float2*)&g_w[(size_t)(ebase + row0 + 8) * 384 + col] = o1;
        }
    }
}

// ---------------- K4: edge messages + scatter-add ----------------------------
__global__ __launch_bounds__(256) void k_scatter(
    const int* __restrict__ eidx, const float* __restrict__ rsh)
{
    const int e = blockIdx.x * 8 + (threadIdx.x >> 5);
    const int lane = threadIdx.x & 31;
    const int dst = eidx[e];
    const int src = eidx[NEDGES + e];
    const float4 r = *(const float4*)(rsh + 4 * e);

    const float* we = g_w + (size_t)e * 384;
    const float* xs = g_xs + src * 128;
    const float* xv = g_xv + src * 192;
    float* as_ = g_accs + dst * 192;
    float* av = g_accv + dst * 576;

    {
        const int ch0 = lane * 4;
        const float4 wss = *(const float4*)(we + ch0);
        const float4 wsv = *(const float4*)(we + 192 + ch0);
        const float4 sj  = *(const float4*)(xs + ch0);
        red4(as_ + ch0, f4scale(f4mul(wss, sj), r.x));
        const float4 base = f4mul(wsv, sj);
        red4(av + ch0,        f4scale(base, r.y));
        red4(av + 192 + ch0,  f4scale(base, r.z));
        red4(av + 384 + ch0,  f4scale(base, r.w));
    }
    if (lane < 16) {
        const int u0 = lane * 4;
        const float4 wvv = *(const float4*)(we + 128 + u0);
        const float4 wvs = *(const float4*)(we + 320 + u0);
        const float4 v0 = *(const float4*)(xv + u0);
        const float4 v1 = *(const float4*)(xv + 64 + u0);
        const float4 v2 = *(const float4*)(xv + 128 + u0);
        float4 vd = f4scale(v0, r.y);
        vd = f4fmas(v1, r.z, vd);
        vd = f4fmas(v2, r.w, vd);
        red4(as_ + 128 + u0, f4scale(f4mul(wvv, vd), INV_SQRT3));
        const float4 wr = f4scale(wvs, r.x);
        red4(av + 128 + u0,        f4mul(wr, v0));
        red4(av + 192 + 128 + u0,  f4mul(wr, v1));
        red4(av + 384 + 128 + u0,  f4mul(wr, v2));
    }
}

// ---------------- K5: gating + node post-mix + residual ----------------------
__global__ __launch_bounds__(320) void k_node_post(
    const float* __restrict__ Wps, const float* __restrict__ Wpv,
    float* __restrict__ out)
{
    __shared__ float gs[8][192];
    __shared__ float gv[8][3][192];
    const int n0 = blockIdx.x * 8;
    const int tid = threadIdx.x;

    for (int idx = tid; idx < 8 * 192; idx += 320) {
        const int i = idx / 192, u = idx % 192;
        const float a = g_accs[(n0 + i) * 192 + u];
        gs[i][u] = silu_f(a);
        const float v0 = g_accv[(n0 + i) * 576 + u];
        const float v1 = g_accv[(n0 + i) * 576 + 192 + u];
        const float v2 = g_accv[(n0 + i) * 576 + 384 + u];
        const float nrm = sqrtf(fmaf(v0, v0, fmaf(v1, v1, fmaf(v2, v2, 1e-12f))));
        const float sg = 1.0f / (1.0f + __expf(-nrm));
        gv[i][0][u] = v0 * sg;
        gv[i][1][u] = v1 * sg;
        gv[i][2][u] = v2 * sg;
    }
    __syncthreads();

    if (tid < 128) {
        const int j = tid;
        float acc[8];
#pragma unroll
        for (int i = 0; i < 8; i++) acc[i] = 0.0f;
        for (int u = 0; u < 192; u++) {
            const float w = Wps[u * 128 + j];
#pragma unroll
            for (int i = 0; i < 8; i++) acc[i] = fmaf(gs[i][u], w, acc[i]);
        }
#pragma unroll
        for (int i = 0; i < 8; i++)
            out[(n0 + i) * 320 + j] =
                g_xs[(n0 + i) * 128 + j] + acc[i] * INV_SQRT_TPC;
    } else {
        const int t = tid - 128;
        const int c = t / 64, vp = t % 64;
        float acc[8];
#pragma unroll
        for (int i = 0; i < 8; i++) acc[i] = 0.0f;
        for (int u = 0; u < 192; u++) {
            const float w = Wpv[u * 64 + vp];
#pragma unroll
            for (int i = 0; i < 8; i++) acc[i] = fmaf(gv[i][c][u], w, acc[i]);
        }
#pragma unroll
        for (int i = 0; i < 8; i++)
            out[(n0 + i) * 320 + 128 + vp * 3 + c] =
                g_xv[(n0 + i) * 192 + c * 64 + vp] + acc[i] * INV_SQRT_TPC;
    }
}

// ---------------- launcher ---------------------------------------------------
extern "C" void kernel_launch(void* const* d_in, const int* in_sizes, int n_in,
                              void* d_out, int out_size)
{
    (void)in_sizes; (void)n_in; (void)out_size;
    const float* nf   = (const float*)d_in[0];
    const float* ea   = (const float*)d_in[1];
    const float* rsh  = (const float*)d_in[2];
    const int*   eidx = (const int*)d_in[3];
    const float* Wps  = (const float*)d_in[4];
    const float* bps  = (const float*)d_in[5];
    const float* Wpv  = (const float*)d_in[6];
    const float* W1   = (const float*)d_in[7];
    const float* b1   = (const float*)d_in[8];
    const float* W2   = (const float*)d_in[9];
    const float* b2   = (const float*)d_in[10];
    const float* Wposts = (const float*)d_in[11];
    const float* Wpostv = (const float*)d_in[12];
    float* out = (float*)d_out;

    cudaFuncSetAttribute(k_mlp2_mma,
                         cudaFuncAttributeMaxDynamicSharedMemorySize,
                         SMEM_MMA_BYTES);

    void* accs_ptr = nullptr;
    void* accv_ptr = nullptr;
    cudaGetSymbolAddress(&accs_ptr, g_accs);
    cudaGetSymbolAddress(&accv_ptr, g_accv);
    cudaMemsetAsync(accs_ptr, 0, sizeof(float) * NNODES * TPCC);
    cudaMemsetAsync(accv_ptr, 0, sizeof(float) * NNODES * 3 * TPCC);

    k_node_pre<<<NNODES / 8, 320>>>(nf, Wps, bps, Wpv);
    k_prep_b<<<48, 256>>>(W2);
    k_edge_mlp1<<<NEDGES / 8, 256>>>(ea, W1, b1);
    k_mlp2_mma<<<NTILES, 256, SMEM_MMA_BYTES>>>(b2);
    k_scatter<<<NEDGES / 8, 256>>>(eidx, rsh);
    k_node_post<<<NNODES / 8, 320>>>(Wposts, Wpostv, out);
}

// round 11
// speedup vs baseline: 1.6656x; 1.0249x over previous
#include <cuda_runtime.h>
#include <cuda_bf16.h>
#include <math.h>
#include <stdint.h>

#define NSC 128
#define NVC 64
#define TPCC 192
#define NNODES 16000
#define NEDGES 256000
#define NTILES 2000           // NEDGES / 128

#define INV_SQRT_NS 0.08838834764831845f
#define INV_SQRT_NV 0.125f
#define INV_SQRT_TPC 0.07216878364870323f
#define INV_SQRT3 0.5773502691896258f

// ---------------- scratch (static device globals; no runtime allocs) --------
__device__ float g_xs[NNODES * NSC];            // [n][128]
__device__ float g_xv[NNODES * 3 * NVC];        // [n][c][64]
__device__ float g_w[NEDGES * 384];             // [e][384]
__device__ float g_accs[NNODES * TPCC];         // [n][192]
__device__ float g_accv[NNODES * 3 * TPCC];     // [n][c][192]
// h split into bf16 hi/lo, row-major [e][128]
__device__ __nv_bfloat16 g_hhi[(size_t)NEDGES * 128];
__device__ __nv_bfloat16 g_hlo[(size_t)NEDGES * 128];
// W2 packed into mma.sync B fragments, STAGE-MAJOR:
// idx = ((cs*8 + s)*8 + jj)*32 + lane,  cs = chunk*2 + half (6 stages)
__device__ uint4 g_Bpk[6 * 8 * 8 * 32];

// ---------------- generic helpers -------------------------------------------
__device__ __forceinline__ float silu_f(float x) {
    return x / (1.0f + __expf(-x));
}
__device__ __forceinline__ float4 f4mul(float4 a, float4 b) {
    return make_float4(a.x * b.x, a.y * b.y, a.z * b.z, a.w * b.w);
}
__device__ __forceinline__ float4 f4scale(float4 a, float s) {
    return make_float4(a.x * s, a.y * s, a.z * s, a.w * s);
}
__device__ __forceinline__ float4 f4fmas(float4 a, float s, float4 c) {
    return make_float4(fmaf(a.x, s, c.x), fmaf(a.y, s, c.y),
                       fmaf(a.z, s, c.z), fmaf(a.w, s, c.w));
}
__device__ __forceinline__ void red4(float* p, float4 v) {
    asm volatile("red.global.add.v4.f32 [%0], {%1, %2, %3, %4};"
                 :: "l"(p), "f"(v.x), "f"(v.y), "f"(v.z), "f"(v.w)
                 : "memory");
}
__device__ __forceinline__ unsigned short bf_bits(__nv_bfloat16 h) {
    return *(unsigned short*)&h;
}
__device__ __forceinline__ void bf_split(float x, unsigned short& hi,
                                         unsigned short& lo) {
    const __nv_bfloat16 h = __float2bfloat16(x);
    const __nv_bfloat16 l = __float2bfloat16(x - __bfloat162float(h));
    hi = bf_bits(h);
    lo = bf_bits(l);
}

// mma.sync m16n8k16 bf16, fp32 accum
__device__ __forceinline__ void mma_bf16(float c[4], const uint4& a,
                                         uint32_t b0, uint32_t b1) {
    asm volatile(
        "mma.sync.aligned.m16n8k16.row.col.f32.bf16.bf16.f32 "
        "{%0,%1,%2,%3}, {%4,%5,%6,%7}, {%8,%9}, {%0,%1,%2,%3};"
        : "+f"(c[0]), "+f"(c[1]), "+f"(c[2]), "+f"(c[3])
        : "r"(a.x), "r"(a.y), "r"(a.z), "r"(a.w), "r"(b0), "r"(b1));
}

// cp.async helpers (sm_80+)
__device__ __forceinline__ void cp16(void* dst_smem, const void* src) {
    uint32_t d = (uint32_t)__cvta_generic_to_shared(dst_smem);
    asm volatile("cp.async.cg.shared.global [%0], [%1], 16;"
                 :: "r"(d), "l"(src) : "memory");
}
#define CP_COMMIT() asm volatile("cp.async.commit_group;" ::: "memory")
#define CP_WAIT(n)  asm volatile("cp.async.wait_group %0;" :: "n"(n) : "memory")

// ---------------- K1: node pre-mix ------------------------------------------
__global__ __launch_bounds__(320) void k_node_pre(
    const float* __restrict__ nf, const float* __restrict__ Ws,
    const float* __restrict__ bs, const float* __restrict__ Wv)
{
    __shared__ float sv[8][320];
    const int n0 = blockIdx.x * 8;
    const int tid = threadIdx.x;

    for (int idx = tid; idx < 8 * 320; idx += 320) {
        sv[idx / 320][idx % 320] = nf[(n0 + idx / 320) * 320 + idx % 320];
    }
    __syncthreads();

    if (tid < 128) {
        const int j = tid;
        float acc[8];
#pragma unroll
        for (int i = 0; i < 8; i++) acc[i] = 0.0f;
        for (int u = 0; u < 128; u++) {
            const float w = Ws[u * 128 + j];
#pragma unroll
            for (int i = 0; i < 8; i++) acc[i] = fmaf(sv[i][u], w, acc[i]);
        }
        const float b = bs[j];
#pragma unroll
        for (int i = 0; i < 8; i++)
            g_xs[(n0 + i) * 128 + j] = fmaf(acc[i], INV_SQRT_NS, b);
    } else {
        const int t = tid - 128;
        const int c = t / 64, vp = t % 64;
        float acc[8];
#pragma unroll
        for (int i = 0; i < 8; i++) acc[i] = 0.0f;
        for (int u = 0; u < 64; u++) {
            const float w = Wv[u * 64 + vp];
#pragma unroll
            for (int i = 0; i < 8; i++)
                acc[i] = fmaf(sv[i][128 + 3 * u + c], w, acc[i]);
        }
#pragma unroll
        for (int i = 0; i < 8; i++)
            g_xv[(n0 + i) * 192 + c * 64 + vp] = acc[i] * INV_SQRT_NV;
    }
}

// ---------------- prep: W2 -> packed B fragments (stage-major) ---------------
__global__ __launch_bounds__(256) void k_prep_b(const float* __restrict__ W2)
{
    const int idx = blockIdx.x * 256 + threadIdx.x;
    if (idx >= 3 * 8 * 16 * 32) return;
    const int lane = idx & 31;
    const int j = (idx >> 5) & 15;       // n-frag within chunk (0..15)
    const int s = (idx >> 9) & 7;
    const int chunk = idx >> 12;

    const int gid = lane >> 2;
    const int tig = lane & 3;
    const int n = chunk * 128 + j * 8 + gid;
    const int k0 = s * 16 + tig * 2;

    unsigned short h0, l0, h1, l1, h2, l2, h3, l3;
    bf_split(W2[k0 * 384 + n],       h0, l0);
    bf_split(W2[(k0 + 1) * 384 + n], h1, l1);
    bf_split(W2[(k0 + 8) * 384 + n], h2, l2);
    bf_split(W2[(k0 + 9) * 384 + n], h3, l3);

    uint4 p;
    p.x = (uint32_t)h0 | ((uint32_t)h1 << 16);   // b0_hi
    p.y = (uint32_t)h2 | ((uint32_t)h3 << 16);   // b1_hi
    p.z = (uint32_t)l0 | ((uint32_t)l1 << 16);   // b0_lo
    p.w = (uint32_t)l2 | ((uint32_t)l3 << 16);   // b1_lo

    const int cs = chunk * 2 + (j >> 3);
    const int jj = j & 7;
    g_Bpk[((cs * 8 + s) * 8 + jj) * 32 + lane] = p;
}

// ---------------- K2: edge MLP layer 1 -> h hi/lo bf16 -----------------------
__global__ __launch_bounds__(256) void k_edge_mlp1(
    const float* __restrict__ ea, const float* __restrict__ W1,
    const float* __restrict__ b1)
{
    __shared__ float W1s[16 * 128];
    __shared__ float b1s[128];
    __shared__ float eas[8][16];
    const int tid = threadIdx.x;
    const int e0 = blockIdx.x * 8;

    for (int idx = tid; idx < 2048; idx += 256) W1s[idx] = W1[idx];
    if (tid < 128) {
        b1s[tid] = b1[tid];
        eas[tid / 16][tid % 16] = ea[e0 * 16 + tid];
    }
    __syncthreads();

    const int i = tid >> 5;
    const int q = (tid & 31) * 4;
    float4 acc = *(const float4*)(b1s + q);
#pragma unroll
    for (int k = 0; k < 16; k++) {
        const float a = eas[i][k];
        const float4 w = *(const float4*)(W1s + k * 128 + q);
        acc = f4fmas(w, a, acc);
    }
    float v[4];
    v[0] = silu_f(acc.x); v[1] = silu_f(acc.y);
    v[2] = silu_f(acc.z); v[3] = silu_f(acc.w);

    unsigned short hb[4], lb[4];
#pragma unroll
    for (int j = 0; j < 4; j++) bf_split(v[j], hb[j], lb[j]);

    const size_t base = (size_t)(e0 + i) * 128 + q;
    uint2 ph, pl;
    ph.x = (uint32_t)hb[0] | ((uint32_t)hb[1] << 16);
    ph.y = (uint32_t)hb[2] | ((uint32_t)hb[3] << 16);
    pl.x = (uint32_t)lb[0] | ((uint32_t)lb[1] << 16);
    pl.y = (uint32_t)lb[2] | ((uint32_t)lb[3] << 16);
    *(uint2*)(g_hhi + base) = ph;
    *(uint2*)(g_hlo + base) = pl;
}

// ---------------- K3: tensor-core GEMM  w = h @ W2 + b2 (bf16x3) -------------
// A fragments held in registers (loaded once through a smem stage that is
// then reused as the cp.async double-buffered B region).
#define SA_STRIDE 136
#define SMEM_A_IMG (128 * SA_STRIDE * 2)            // 34816 per image
#define SMEM_REGION (2 * SMEM_A_IMG)                // 69632 >= 2*32768
#define SMEM_B_BYTES 32768
#define SMEM_BIAS_OFF SMEM_REGION                   // 69632
#define SMEM_MMA_BYTES (SMEM_BIAS_OFF + 1536)       // 71168
__global__ __launch_bounds__(256, 2) void k_mlp2_mma(const float* __restrict__ b2)
{
    extern __shared__ unsigned char smem[];
    __nv_bfloat16* sAh = (__nv_bfloat16*)smem;
    __nv_bfloat16* sAl = (__nv_bfloat16*)(smem + SMEM_A_IMG);
    float* sbias = (float*)(smem + SMEM_BIAS_OFF);

    const int tid = threadIdx.x;
    const int warp = tid >> 5;
    const int lane = tid & 31;
    const int tile = blockIdx.x;
    const int gid = lane >> 2;       // 0..7
    const int tig = lane & 3;        // 0..3
    const int row0 = warp * 16 + gid;

    // ---- stage A once, pull fragments into registers ----
    {
        const uint2* ghh = (const uint2*)(g_hhi + (size_t)tile * 16384);
        const uint2* ghl = (const uint2*)(g_hlo + (size_t)tile * 16384);
        for (int i = tid; i < 4096; i += 256) {
            const int r = i >> 5, q = (i & 31) * 4;
            *(uint2*)&sAh[r * SA_STRIDE + q] = ghh[i];
            *(uint2*)&sAl[r * SA_STRIDE + q] = ghl[i];
        }
    }
    for (int i = tid; i < 384; i += 256) sbias[i] = b2[i];
    __syncthreads();

    uint4 ah[8], al[8];
#pragma unroll
    for (int s = 0; s < 8; s++) {
        const int kb = s * 16 + tig * 2;
        ah[s].x = *(const uint32_t*)&sAh[row0 * SA_STRIDE + kb];
        ah[s].y = *(const uint32_t*)&sAh[(row0 + 8) * SA_STRIDE + kb];
        ah[s].z = *(const uint32_t*)&sAh[row0 * SA_STRIDE + kb + 8];
        ah[s].w = *(const uint32_t*)&sAh[(row0 + 8) * SA_STRIDE + kb + 8];
        al[s].x = *(const uint32_t*)&sAl[row0 * SA_STRIDE + kb];
        al[s].y = *(const uint32_t*)&sAl[(row0 + 8) * SA_STRIDE + kb];
        al[s].z = *(const uint32_t*)&sAl[row0 * SA_STRIDE + kb + 8];
        al[s].w = *(const uint32_t*)&sAl[(row0 + 8) * SA_STRIDE + kb + 8];
    }
    __syncthreads();     // all warps done reading A region -> reuse for B

    uint4* sB[2] = { (uint4*)smem, (uint4*)(smem + SMEM_B_BYTES) };

    // prefetch stage 0 (2048 uint4, 8 per thread, contiguous)
    {
        const uint4* src = g_Bpk;
#pragma unroll
        for (int i = 0; i < 8; i++)
            cp16(&sB[0][tid + i * 256], &src[tid + i * 256]);
        CP_COMMIT();
    }

    const int ebase = tile * 128;

    for (int cs = 0; cs < 6; cs++) {
        if (cs < 5) {
            const uint4* src = g_Bpk + (cs + 1) * 2048;
            uint4* dst = sB[(cs + 1) & 1];
#pragma unroll
            for (int i = 0; i < 8; i++)
                cp16(&dst[tid + i * 256], &src[tid + i * 256]);
            CP_COMMIT();
            CP_WAIT(1);
        } else {
            CP_WAIT(0);
        }
        __syncthreads();    // stage cs visible to all threads

        const uint4* bb = sB[cs & 1];
        float c[8][4];
#pragma unroll
        for (int j = 0; j < 8; j++)
#pragma unroll
            for (int q = 0; q < 4; q++) c[j][q] = 0.0f;

#pragma unroll
        for (int s = 0; s < 8; s++) {
#pragma unroll
            for (int j = 0; j < 8; j++) {
                const uint4 b = bb[(s * 8 + j) * 32 + lane];
                mma_bf16(c[j], ah[s], b.x, b.y);   // hi * hi
                mma_bf16(c[j], ah[s], b.z, b.w);   // hi * lo
                mma_bf16(c[j], al[s], b.x, b.y);   // lo * hi
            }
        }

        // epilogue: this stage's 64 cols with bias
        const int chunk = cs >> 1, half = cs & 1;
#pragma unroll
        for (int j = 0; j < 8; j++) {
            const int col = chunk * 128 + half * 64 + j * 8 + tig * 2;
            const float bx = sbias[col], by = sbias[col + 1];
            float2 o0 = make_float2(c[j][0] + bx, c[j][1] + by);
            float2 o1 = make_float2(c[j][2] + bx, c[j][3] + by);
            *(float2*)&g_w[(size_t)(ebase + row0) * 384 + col] = o0;
            *(float2*)&g_w[(size_t)(ebase + row0 + 8) * 384 + col] = o1;
        }
        __syncthreads();    // done reading buf before it is overwritten
    }
}

// ---------------- K4: edge messages + scatter-add ----------------------------
__global__ __launch_bounds__(256) void k_scatter(
    const int* __restrict__ eidx, const float* __restrict__ rsh)
{
    const int e = blockIdx.x * 8 + (threadIdx.x >> 5);
    const int lane = threadIdx.x & 31;
    const int dst = eidx[e];
    const int src = eidx[NEDGES + e];
    const float4 r = *(const float4*)(rsh + 4 * e);

    const float* we = g_w + (size_t)e * 384;
    const float* xs = g_xs + src * 128;
    const float* xv = g_xv + src * 192;
    float* as_ = g_accs + dst * 192;
    float* av = g_accv + dst * 576;

    {
        const int ch0 = lane * 4;
        const float4 wss = *(const float4*)(we + ch0);
        const float4 wsv = *(const float4*)(we + 192 + ch0);
        const float4 sj  = *(const float4*)(xs + ch0);
        red4(as_ + ch0, f4scale(f4mul(wss, sj), r.x));
        const float4 base = f4mul(wsv, sj);
        red4(av + ch0,        f4scale(base, r.y));
        red4(av + 192 + ch0,  f4scale(base, r.z));
        red4(av + 384 + ch0,  f4scale(base, r.w));
    }
    if (lane < 16) {
        const int u0 = lane * 4;
        const float4 wvv = *(const float4*)(we + 128 + u0);
        const float4 wvs = *(const float4*)(we + 320 + u0);
        const float4 v0 = *(const float4*)(xv + u0);
        const float4 v1 = *(const float4*)(xv + 64 + u0);
        const float4 v2 = *(const float4*)(xv + 128 + u0);
        float4 vd = f4scale(v0, r.y);
        vd = f4fmas(v1, r.z, vd);
        vd = f4fmas(v2, r.w, vd);
        red4(as_ + 128 + u0, f4scale(f4mul(wvv, vd), INV_SQRT3));
        const float4 wr = f4scale(wvs, r.x);
        red4(av + 128 + u0,        f4mul(wr, v0));
        red4(av + 192 + 128 + u0,  f4mul(wr, v1));
        red4(av + 384 + 128 + u0,  f4mul(wr, v2));
    }
}

// ---------------- K5: gating + node post-mix + residual ----------------------
__global__ __launch_bounds__(320) void k_node_post(
    const float* __restrict__ Wps, const float* __restrict__ Wpv,
    float* __restrict__ out)
{
    __shared__ float gs[8][192];
    __shared__ float gv[8][3][192];
    const int n0 = blockIdx.x * 8;
    const int tid = threadIdx.x;

    for (int idx = tid; idx < 8 * 192; idx += 320) {
        const int i = idx / 192, u = idx % 192;
        const float a = g_accs[(n0 + i) * 192 + u];
        gs[i][u] = silu_f(a);
        const float v0 = g_accv[(n0 + i) * 576 + u];
        const float v1 = g_accv[(n0 + i) * 576 + 192 + u];
        const float v2 = g_accv[(n0 + i) * 576 + 384 + u];
        const float nrm = sqrtf(fmaf(v0, v0, fmaf(v1, v1, fmaf(v2, v2, 1e-12f))));
        const float sg = 1.0f / (1.0f + __expf(-nrm));
        gv[i][0][u] = v0 * sg;
        gv[i][1][u] = v1 * sg;
        gv[i][2][u] = v2 * sg;
    }
    __syncthreads();

    if (tid < 128) {
        const int j = tid;
        float acc[8];
#pragma unroll
        for (int i = 0; i < 8; i++) acc[i] = 0.0f;
        for (int u = 0; u < 192; u++) {
            const float w = Wps[u * 128 + j];
#pragma unroll
            for (int i = 0; i < 8; i++) acc[i] = fmaf(gs[i][u], w, acc[i]);
        }
#pragma unroll
        for (int i = 0; i < 8; i++)
            out[(n0 + i) * 320 + j] =
                g_xs[(n0 + i) * 128 + j] + acc[i] * INV_SQRT_TPC;
    } else {
        const int t = tid - 128;
        const int c = t / 64, vp = t % 64;
        float acc[8];
#pragma unroll
        for (int i = 0; i < 8; i++) acc[i] = 0.0f;
        for (int u = 0; u < 192; u++) {
            const float w = Wpv[u * 64 + vp];
#pragma unroll
            for (int i = 0; i < 8; i++) acc[i] = fmaf(gv[i][c][u], w, acc[i]);
        }
#pragma unroll
        for (int i = 0; i < 8; i++)
            out[(n0 + i) * 320 + 128 + vp * 3 + c] =
                g_xv[(n0 + i) * 192 + c * 64 + vp] + acc[i] * INV_SQRT_TPC;
    }
}

// ---------------- launcher ---------------------------------------------------
extern "C" void kernel_launch(void* const* d_in, const int* in_sizes, int n_in,
                              void* d_out, int out_size)
{
    (void)in_sizes; (void)n_in; (void)out_size;
    const float* nf   = (const float*)d_in[0];
    const float* ea   = (const float*)d_in[1];
    const float* rsh  = (const float*)d_in[2];
    const int*   eidx = (const int*)d_in[3];
    const float* Wps  = (const float*)d_in[4];
    const float* bps  = (const float*)d_in[5];
    const float* Wpv  = (const float*)d_in[6];
    const float* W1   = (const float*)d_in[7];
    const float* b1   = (const float*)d_in[8];
    const float* W2   = (const float*)d_in[9];
    const float* b2   = (const float*)d_in[10];
    const float* Wposts = (const float*)d_in[11];
    const float* Wpostv = (const float*)d_in[12];
    float* out = (float*)d_out;

    cudaFuncSetAttribute(k_mlp2_mma,
                         cudaFuncAttributeMaxDynamicSharedMemorySize,
                         SMEM_MMA_BYTES);

    void* accs_ptr = nullptr;
    void* accv_ptr = nullptr;
    cudaGetSymbolAddress(&accs_ptr, g_accs);
    cudaGetSymbolAddress(&accv_ptr, g_accv);
    cudaMemsetAsync(accs_ptr, 0, sizeof(float) * NNODES * TPCC);
    cudaMemsetAsync(accv_ptr, 0, sizeof(float) * NNODES * 3 * TPCC);

    k_node_pre<<<NNODES / 8, 320>>>(nf, Wps, bps, Wpv);
    k_prep_b<<<48, 256>>>(W2);
    k_edge_mlp1<<<NEDGES / 8, 256>>>(ea, W1, b1);
    k_mlp2_mma<<<NTILES, 256, SMEM_MMA_BYTES>>>(b2);
    k_scatter<<<NEDGES / 8, 256>>>(eidx, rsh);
    k_node_post<<<NNODES / 8, 320>>>(Wposts, Wpostv, out);
}

// round 12
// speedup vs baseline: 1.7238x; 1.0350x over previous
#include <cuda_runtime.h>
#include <cuda_bf16.h>
#include <math.h>
#include <stdint.h>

#define NSC 128
#define NVC 64
#define TPCC 192
#define NNODES 16000
#define NEDGES 256000
#define NTILES 2000           // NEDGES / 128

#define INV_SQRT_NS 0.08838834764831845f
#define INV_SQRT_NV 0.125f
#define INV_SQRT_TPC 0.07216878364870323f
#define INV_SQRT3 0.5773502691896258f

// ---------------- scratch (static device globals; no runtime allocs) --------
__device__ float g_xs[NNODES * NSC];            // [n][128]
__device__ float g_xv[NNODES * 3 * NVC];        // [n][c][64]
__device__ float g_accs[NNODES * TPCC];         // [n][192]
__device__ float g_accv[NNODES * 3 * TPCC];     // [n][c][192]
// h split into bf16 hi/lo, row-major [e][128]
__device__ __nv_bfloat16 g_hhi[(size_t)NEDGES * 128];
__device__ __nv_bfloat16 g_hlo[(size_t)NEDGES * 128];
// W2 packed into mma.sync B fragments, STAGE-MAJOR:
// idx = ((cs*8 + s)*8 + jj)*32 + lane,  cs = chunk*2 + half (6 stages)
__device__ uint4 g_Bpk[6 * 8 * 8 * 32];

// ---------------- generic helpers -------------------------------------------
__device__ __forceinline__ float silu_f(float x) {
    return x / (1.0f + __expf(-x));
}
__device__ __forceinline__ float4 f4mul(float4 a, float4 b) {
    return make_float4(a.x * b.x, a.y * b.y, a.z * b.z, a.w * b.w);
}
__device__ __forceinline__ float4 f4scale(float4 a, float s) {
    return make_float4(a.x * s, a.y * s, a.z * s, a.w * s);
}
__device__ __forceinline__ float4 f4fmas(float4 a, float s, float4 c) {
    return make_float4(fmaf(a.x, s, c.x), fmaf(a.y, s, c.y),
                       fmaf(a.z, s, c.z), fmaf(a.w, s, c.w));
}
__device__ __forceinline__ void red4(float* p, float4 v) {
    asm volatile("red.global.add.v4.f32 [%0], {%1, %2, %3, %4};"
                 :: "l"(p), "f"(v.x), "f"(v.y), "f"(v.z), "f"(v.w)
                 : "memory");
}
__device__ __forceinline__ unsigned short bf_bits(__nv_bfloat16 h) {
    return *(unsigned short*)&h;
}
__device__ __forceinline__ void bf_split(float x, unsigned short& hi,
                                         unsigned short& lo) {
    const __nv_bfloat16 h = __float2bfloat16(x);
    const __nv_bfloat16 l = __float2bfloat16(x - __bfloat162float(h));
    hi = bf_bits(h);
    lo = bf_bits(l);
}

// mma.sync m16n8k16 bf16, fp32 accum
__device__ __forceinline__ void mma_bf16(float c[4], const uint4& a,
                                         uint32_t b0, uint32_t b1) {
    asm volatile(
        "mma.sync.aligned.m16n8k16.row.col.f32.bf16.bf16.f32 "
        "{%0,%1,%2,%3}, {%4,%5,%6,%7}, {%8,%9}, {%0,%1,%2,%3};"
        : "+f"(c[0]), "+f"(c[1]), "+f"(c[2]), "+f"(c[3])
        : "r"(a.x), "r"(a.y), "r"(a.z), "r"(a.w), "r"(b0), "r"(b1));
}

// cp.async helpers (sm_80+)
__device__ __forceinline__ void cp16(void* dst_smem, const void* src) {
    uint32_t d = (uint32_t)__cvta_generic_to_shared(dst_smem);
    asm volatile("cp.async.cg.shared.global [%0], [%1], 16;"
                 :: "r"(d), "l"(src) : "memory");
}
#define CP_COMMIT() asm volatile("cp.async.commit_group;" ::: "memory")
#define CP_WAIT(n)  asm volatile("cp.async.wait_group %0;" :: "n"(n) : "memory")

// ---------------- K1: node pre-mix ------------------------------------------
__global__ __launch_bounds__(320) void k_node_pre(
    const float* __restrict__ nf, const float* __restrict__ Ws,
    const float* __restrict__ bs, const float* __restrict__ Wv)
{
    __shared__ float sv[8][320];
    const int n0 = blockIdx.x * 8;
    const int tid = threadIdx.x;

    for (int idx = tid; idx < 8 * 320; idx += 320) {
        sv[idx / 320][idx % 320] = nf[(n0 + idx / 320) * 320 + idx % 320];
    }
    __syncthreads();

    if (tid < 128) {
        const int j = tid;
        float acc[8];
#pragma unroll
        for (int i = 0; i < 8; i++) acc[i] = 0.0f;
        for (int u = 0; u < 128; u++) {
            const float w = Ws[u * 128 + j];
#pragma unroll
            for (int i = 0; i < 8; i++) acc[i] = fmaf(sv[i][u], w, acc[i]);
        }
        const float b = bs[j];
#pragma unroll
        for (int i = 0; i < 8; i++)
            g_xs[(n0 + i) * 128 + j] = fmaf(acc[i], INV_SQRT_NS, b);
    } else {
        const int t = tid - 128;
        const int c = t / 64, vp = t % 64;
        float acc[8];
#pragma unroll
        for (int i = 0; i < 8; i++) acc[i] = 0.0f;
        for (int u = 0; u < 64; u++) {
            const float w = Wv[u * 64 + vp];
#pragma unroll
            for (int i = 0; i < 8; i++)
                acc[i] = fmaf(sv[i][128 + 3 * u + c], w, acc[i]);
        }
#pragma unroll
        for (int i = 0; i < 8; i++)
            g_xv[(n0 + i) * 192 + c * 64 + vp] = acc[i] * INV_SQRT_NV;
    }
}

// ---------------- prep: W2 -> packed B fragments (stage-major) ---------------
__global__ __launch_bounds__(256) void k_prep_b(const float* __restrict__ W2)
{
    const int idx = blockIdx.x * 256 + threadIdx.x;
    if (idx >= 3 * 8 * 16 * 32) return;
    const int lane = idx & 31;
    const int j = (idx >> 5) & 15;       // n-frag within chunk (0..15)
    const int s = (idx >> 9) & 7;
    const int chunk = idx >> 12;

    const int gid = lane >> 2;
    const int tig = lane & 3;
    const int n = chunk * 128 + j * 8 + gid;
    const int k0 = s * 16 + tig * 2;

    unsigned short h0, l0, h1, l1, h2, l2, h3, l3;
    bf_split(W2[k0 * 384 + n],       h0, l0);
    bf_split(W2[(k0 + 1) * 384 + n], h1, l1);
    bf_split(W2[(k0 + 8) * 384 + n], h2, l2);
    bf_split(W2[(k0 + 9) * 384 + n], h3, l3);

    uint4 p;
    p.x = (uint32_t)h0 | ((uint32_t)h1 << 16);   // b0_hi
    p.y = (uint32_t)h2 | ((uint32_t)h3 << 16);   // b1_hi
    p.z = (uint32_t)l0 | ((uint32_t)l1 << 16);   // b0_lo
    p.w = (uint32_t)l2 | ((uint32_t)l3 << 16);   // b1_lo

    const int cs = chunk * 2 + (j >> 3);
    const int jj = j & 7;
    g_Bpk[((cs * 8 + s) * 8 + jj) * 32 + lane] = p;
}

// ---------------- K2: edge MLP layer 1 -> h hi/lo bf16 -----------------------
__global__ __launch_bounds__(256) void k_edge_mlp1(
    const float* __restrict__ ea, const float* __restrict__ W1,
    const float* __restrict__ b1)
{
    __shared__ float W1s[16 * 128];
    __shared__ float b1s[128];
    __shared__ float eas[8][16];
    const int tid = threadIdx.x;
    const int e0 = blockIdx.x * 8;

    for (int idx = tid; idx < 2048; idx += 256) W1s[idx] = W1[idx];
    if (tid < 128) {
        b1s[tid] = b1[tid];
        eas[tid / 16][tid % 16] = ea[e0 * 16 + tid];
    }
    __syncthreads();

    const int i = tid >> 5;
    const int q = (tid & 31) * 4;
    float4 acc = *(const float4*)(b1s + q);
#pragma unroll
    for (int k = 0; k < 16; k++) {
        const float a = eas[i][k];
        const float4 w = *(const float4*)(W1s + k * 128 + q);
        acc = f4fmas(w, a, acc);
    }
    float v[4];
    v[0] = silu_f(acc.x); v[1] = silu_f(acc.y);
    v[2] = silu_f(acc.z); v[3] = silu_f(acc.w);

    unsigned short hb[4], lb[4];
#pragma unroll
    for (int j = 0; j < 4; j++) bf_split(v[j], hb[j], lb[j]);

    const size_t base = (size_t)(e0 + i) * 128 + q;
    uint2 ph, pl;
    ph.x = (uint32_t)hb[0] | ((uint32_t)hb[1] << 16);
    ph.y = (uint32_t)hb[2] | ((uint32_t)hb[3] << 16);
    pl.x = (uint32_t)lb[0] | ((uint32_t)lb[1] << 16);
    pl.y = (uint32_t)lb[2] | ((uint32_t)lb[3] << 16);
    *(uint2*)(g_hhi + base) = ph;
    *(uint2*)(g_hlo + base) = pl;
}

// ---------------- K3: FUSED tensor GEMM + message scatter --------------------
#define SA_STRIDE 136
#define SMEM_A_IMG (128 * SA_STRIDE * 2)            // 34816 per image
#define SMEM_B_BYTES 32768
#define SMEM_WS_OFF (2 * SMEM_A_IMG)                // 69632
#define WS_STRIDE 68
#define SMEM_BIAS_OFF (SMEM_WS_OFF + 128 * WS_STRIDE * 4)   // 104448
#define SMEM_EIDX_OFF (SMEM_BIAS_OFF + 1536)        // 105984
#define SMEM_R_OFF    (SMEM_EIDX_OFF + 1024)        // 107008
#define SMEM_MMA_BYTES (SMEM_R_OFF + 2048)          // 109056
__global__ __launch_bounds__(256, 2) void k_mlp2_fused(
    const float* __restrict__ b2,
    const int* __restrict__ eidx, const float* __restrict__ rsh)
{
    extern __shared__ unsigned char smem[];
    __nv_bfloat16* sAh = (__nv_bfloat16*)smem;
    __nv_bfloat16* sAl = (__nv_bfloat16*)(smem + SMEM_A_IMG);
    float* ws = (float*)(smem + SMEM_WS_OFF);
    float* sbias = (float*)(smem + SMEM_BIAS_OFF);
    int* sDst = (int*)(smem + SMEM_EIDX_OFF);
    int* sSrc = sDst + 128;
    float4* sR4 = (float4*)(smem + SMEM_R_OFF);

    const int tid = threadIdx.x;
    const int warp = tid >> 5;
    const int lane = tid & 31;
    const int tile = blockIdx.x;
    const int gid = lane >> 2;
    const int tig = lane & 3;
    const int row0 = warp * 16 + gid;

    // ---- stage A once, pull fragments into registers ----
    {
        const uint2* ghh = (const uint2*)(g_hhi + (size_t)tile * 16384);
        const uint2* ghl = (const uint2*)(g_hlo + (size_t)tile * 16384);
        for (int i = tid; i < 4096; i += 256) {
            const int r = i >> 5, q = (i & 31) * 4;
            *(uint2*)&sAh[r * SA_STRIDE + q] = ghh[i];
            *(uint2*)&sAl[r * SA_STRIDE + q] = ghl[i];
        }
    }
    for (int i = tid; i < 384; i += 256) sbias[i] = b2[i];
    if (tid < 128) {
        sDst[tid] = eidx[tile * 128 + tid];
        sSrc[tid] = eidx[NEDGES + tile * 128 + tid];
        sR4[tid] = *(const float4*)(rsh + 4 * (tile * 128 + tid));
    }
    __syncthreads();

    uint4 ah[8], al[8];
#pragma unroll
    for (int s = 0; s < 8; s++) {
        const int kb = s * 16 + tig * 2;
        ah[s].x = *(const uint32_t*)&sAh[row0 * SA_STRIDE + kb];
        ah[s].y = *(const uint32_t*)&sAh[(row0 + 8) * SA_STRIDE + kb];
        ah[s].z = *(const uint32_t*)&sAh[row0 * SA_STRIDE + kb + 8];
        ah[s].w = *(const uint32_t*)&sAh[(row0 + 8) * SA_STRIDE + kb + 8];
        al[s].x = *(const uint32_t*)&sAl[row0 * SA_STRIDE + kb];
        al[s].y = *(const uint32_t*)&sAl[(row0 + 8) * SA_STRIDE + kb];
        al[s].z = *(const uint32_t*)&sAl[row0 * SA_STRIDE + kb + 8];
        al[s].w = *(const uint32_t*)&sAl[(row0 + 8) * SA_STRIDE + kb + 8];
    }
    __syncthreads();     // A region released -> reused as B double buffer

    uint4* sB[2] = { (uint4*)smem, (uint4*)(smem + SMEM_B_BYTES) };

    {
        const uint4* src = g_Bpk;
#pragma unroll
        for (int i = 0; i < 8; i++)
            cp16(&sB[0][tid + i * 256], &src[tid + i * 256]);
        CP_COMMIT();
    }

    for (int cs = 0; cs < 6; cs++) {
        if (cs < 5) {
            const uint4* src = g_Bpk + (cs + 1) * 2048;
            uint4* dst = sB[(cs + 1) & 1];
#pragma unroll
            for (int i = 0; i < 8; i++)
                cp16(&dst[tid + i * 256], &src[tid + i * 256]);
            CP_COMMIT();
            CP_WAIT(1);
        } else {
            CP_WAIT(0);
        }
        __syncthreads();

        const uint4* bb = sB[cs & 1];
        float c[8][4];
#pragma unroll
        for (int j = 0; j < 8; j++)
#pragma unroll
            for (int q = 0; q < 4; q++) c[j][q] = 0.0f;

#pragma unroll
        for (int s = 0; s < 8; s++) {
#pragma unroll
            for (int j = 0; j < 8; j++) {
                const uint4 b = bb[(s * 8 + j) * 32 + lane];
                mma_bf16(c[j], ah[s], b.x, b.y);
                mma_bf16(c[j], ah[s], b.z, b.w);
                mma_bf16(c[j], al[s], b.x, b.y);
            }
        }

        // ---- stage w to warp-local ws rows (bias added) ----
        const int cbase = cs * 64;
#pragma unroll
        for (int j = 0; j < 8; j++) {
            const int cl = j * 8 + tig * 2;
            const float bx = sbias[cbase + cl], by = sbias[cbase + cl + 1];
            *(float2*)&ws[row0 * WS_STRIDE + cl] =
                make_float2(c[j][0] + bx, c[j][1] + by);
            *(float2*)&ws[(row0 + 8) * WS_STRIDE + cl] =
                make_float2(c[j][2] + bx, c[j][3] + by);
        }
        __syncwarp();

        // ---- scatter this stage's 64 cols for this warp's 16 edges ----
        const int halfw = lane >> 4;
        const int cl = (lane & 15) * 4;
#pragma unroll
        for (int it = 0; it < 8; it++) {
            const int t = warp * 16 + it * 2 + halfw;
            const int dst = sDst[t];
            const int src = sSrc[t];
            const float4 r = sR4[t];
            const float4 w = *(const float4*)&ws[t * WS_STRIDE + cl];
            float* as_ = g_accs + dst * 192;
            float* av = g_accv + dst * 576;

            if (cs < 2) {
                const int col = cs * 64 + cl;
                const float4 sj = *(const float4*)(g_xs + src * 128 + col);
                red4(as_ + col, f4scale(f4mul(w, sj), r.x));
            } else if (cs == 2) {
                const int u = cl;
                const float* xv = g_xv + src * 192;
                const float4 v0 = *(const float4*)(xv + u);
                const float4 v1 = *(const float4*)(xv + 64 + u);
                const float4 v2 = *(const float4*)(xv + 128 + u);
                float4 vd = f4scale(v0, r.y);
                vd = f4fmas(v1, r.z, vd);
                vd = f4fmas(v2, r.w, vd);
                red4(as_ + 128 + u, f4scale(f4mul(w, vd), INV_SQRT3));
            } else if (cs < 5) {
                const int s = (cs - 3) * 64 + cl;
                const float4 sj = *(const float4*)(g_xs + src * 128 + s);
                const float4 base = f4mul(w, sj);
                red4(av + s,       f4scale(base, r.y));
                red4(av + 192 + s, f4scale(base, r.z));
                red4(av + 384 + s, f4scale(base, r.w));
            } else {
                const int u = cl;
                const float* xv = g_xv + src * 192;
                const float4 wr = f4scale(w, r.x);
                red4(av + 128 + u, f4mul(wr, *(const float4*)(xv + u)));
                red4(av + 320 + u, f4mul(wr, *(const float4*)(xv + 64 + u)));
                red4(av + 512 + u, f4mul(wr, *(const float4*)(xv + 128 + u)));
            }
        }
        __syncthreads();
    }
}

// ---------------- K5: gating + node post-mix + residual (f4 inner loops) -----
__global__ __launch_bounds__(320) void k_node_post(
    const float* __restrict__ Wps, const float* __restrict__ Wpv,
    float* __restrict__ out)
{
    __shared__ float gs[8][192];
    __shared__ float gv[8][3][192];
    const int n0 = blockIdx.x * 8;
    const int tid = threadIdx.x;

    for (int idx = tid; idx < 8 * 192; idx += 320) {
        const int i = idx / 192, u = idx % 192;
        const float a = g_accs[(n0 + i) * 192 + u];
        gs[i][u] = silu_f(a);
        const float v0 = g_accv[(n0 + i) * 576 + u];
        const float v1 = g_accv[(n0 + i) * 576 + 192 + u];
        const float v2 = g_accv[(n0 + i) * 576 + 384 + u];
        const float nrm = sqrtf(fmaf(v0, v0, fmaf(v1, v1, fmaf(v2, v2, 1e-12f))));
        const float sg = 1.0f / (1.0f + __expf(-nrm));
        gv[i][0][u] = v0 * sg;
        gv[i][1][u] = v1 * sg;
        gv[i][2][u] = v2 * sg;
    }
    __syncthreads();

    if (tid < 128) {
        const int j = tid;
        float acc[8];
#pragma unroll
        for (int i = 0; i < 8; i++) acc[i] = 0.0f;
        for (int u = 0; u < 192; u += 4) {
            float4 w;
            w.x = Wps[u * 128 + j];
            w.y = Wps[(u + 1) * 128 + j];
            w.z = Wps[(u + 2) * 128 + j];
            w.w = Wps[(u + 3) * 128 + j];
#pragma unroll
            for (int i = 0; i < 8; i++) {
                const float4 g = *(const float4*)&gs[i][u];
                acc[i] = fmaf(g.x, w.x, acc[i]);
                acc[i] = fmaf(g.y, w.y, acc[i]);
                acc[i] = fmaf(g.z, w.z, acc[i]);
                acc[i] = fmaf(g.w, w.w, acc[i]);
            }
        }
#pragma unroll
        for (int i = 0; i < 8; i++)
            out[(n0 + i) * 320 + j] =
                g_xs[(n0 + i) * 128 + j] + acc[i] * INV_SQRT_TPC;
    } else {
        const int t = tid - 128;
        const int c = t / 64, vp = t % 64;
        float acc[8];
#pragma unroll
        for (int i = 0; i < 8; i++) acc[i] = 0.0f;
        for (int u = 0; u < 192; u += 4) {
            float4 w;
            w.x = Wpv[u * 64 + vp];
            w.y = Wpv[(u + 1) * 64 + vp];
            w.z = Wpv[(u + 2) * 64 + vp];
            w.w = Wpv[(u + 3) * 64 + vp];
#pragma unroll
            for (int i = 0; i < 8; i++) {
                const float4 g = *(const float4*)&gv[i][c][u];
                acc[i] = fmaf(g.x, w.x, acc[i]);
                acc[i] = fmaf(g.y, w.y, acc[i]);
                acc[i] = fmaf(g.z, w.z, acc[i]);
                acc[i] = fmaf(g.w, w.w, acc[i]);
            }
        }
#pragma unroll
        for (int i = 0; i < 8; i++)
            out[(n0 + i) * 320 + 128 + vp * 3 + c] =
                g_xv[(n0 + i) * 192 + c * 64 + vp] + acc[i] * INV_SQRT_TPC;
    }
}

// ---------------- launcher ---------------------------------------------------
extern "C" void kernel_launch(void* const* d_in, const int* in_sizes, int n_in,
                              void* d_out, int out_size)
{
    (void)in_sizes; (void)n_in; (void)out_size;
    const float* nf   = (const float*)d_in[0];
    const float* ea   = (const float*)d_in[1];
    const float* rsh  = (const float*)d_in[2];
    const int*   eidx = (const int*)d_in[3];
    const float* Wps  = (const float*)d_in[4];
    const float* bps  = (const float*)d_in[5];
    const float* Wpv  = (const float*)d_in[6];
    const float* W1   = (const float*)d_in[7];
    const float* b1   = (const float*)d_in[8];
    const float* W2   = (const float*)d_in[9];
    const float* b2   = (const float*)d_in[10];
    const float* Wposts = (const float*)d_in[11];
    const float* Wpostv = (const float*)d_in[12];
    float* out = (float*)d_out;

    cudaFuncSetAttribute(k_mlp2_fused,
                         cudaFuncAttributeMaxDynamicSharedMemorySize,
                         SMEM_MMA_BYTES);

    void* accs_ptr = nullptr;
    void* accv_ptr = nullptr;
    cudaGetSymbolAddress(&accs_ptr, g_accs);
    cudaGetSymbolAddress(&accv_ptr, g_accv);
    cudaMemsetAsync(accs_ptr, 0, sizeof(float) * NNODES * TPCC);
    cudaMemsetAsync(accv_ptr, 0, sizeof(float) * NNODES * 3 * TPCC);

    k_node_pre<<<NNODES / 8, 320>>>(nf, Wps, bps, Wpv);
    k_prep_b<<<48, 256>>>(W2);
    k_edge_mlp1<<<NEDGES / 8, 256>>>(ea, W1, b1);
    k_mlp2_fused<<<NTILES, 256, SMEM_MMA_BYTES>>>(b2, eidx, rsh);
    k_node_post<<<NNODES / 8, 320>>>(Wposts, Wpostv, out);
}

// round 13
// speedup vs baseline: 1.8024x; 1.0456x over previous
#include <cuda_runtime.h>
#include <cuda_bf16.h>
#include <math.h>
#include <stdint.h>

#define NSC 128
#define NVC 64
#define TPCC 192
#define NNODES 16000
#define NEDGES 256000
#define NTILES 2000           // NEDGES / 128

#define INV_SQRT_NS 0.08838834764831845f
#define INV_SQRT_NV 0.125f
#define INV_SQRT_TPC 0.07216878364870323f
#define INV_SQRT3 0.5773502691896258f

// ---------------- scratch (static device globals; no runtime allocs) --------
__device__ float g_xs[NNODES * NSC];            // [n][128]
__device__ float g_xv[NNODES * 3 * NVC];        // [n][c][64]
__device__ float g_accs[NNODES * TPCC];         // [n][192]
__device__ float g_accv[NNODES * 3 * TPCC];     // [n][c][192]
// h split into bf16 hi/lo, row-major [e][128]
__device__ __nv_bfloat16 g_hhi[(size_t)NEDGES * 128];
__device__ __nv_bfloat16 g_hlo[(size_t)NEDGES * 128];
// W2 packed into mma.sync B fragments, PERMUTED stage-major:
// idx = ((cs*8 + s)*8 + jj)*32 + lane  (cs = 0..5; cols paired per stage)
__device__ uint4 g_Bpk[6 * 8 * 8 * 32];

// stage column permutation: stage cs, within-stage col sc (0..63) -> W2 col.
// S0-3: [ w_ss0[cs*32 : +32] | w_sv1[cs*32 : +32] ]   (share xs gather)
// S4-5: [ w_vv0[(cs-4)*32:+32] | w_vs1[(cs-4)*32:+32] ] (share xv gather)
__host__ __device__ __forceinline__ int perm_col(int cs, int sc) {
    if (cs < 4)
        return (sc < 32) ? (cs * 32 + sc) : (192 + cs * 32 + (sc - 32));
    else
        return (sc < 32) ? (128 + (cs - 4) * 32 + sc)
                         : (320 + (cs - 4) * 32 + (sc - 32));
}

// ---------------- generic helpers -------------------------------------------
__device__ __forceinline__ float silu_f(float x) {
    return x / (1.0f + __expf(-x));
}
__device__ __forceinline__ float4 f4mul(float4 a, float4 b) {
    return make_float4(a.x * b.x, a.y * b.y, a.z * b.z, a.w * b.w);
}
__device__ __forceinline__ float4 f4scale(float4 a, float s) {
    return make_float4(a.x * s, a.y * s, a.z * s, a.w * s);
}
__device__ __forceinline__ float4 f4fmas(float4 a, float s, float4 c) {
    return make_float4(fmaf(a.x, s, c.x), fmaf(a.y, s, c.y),
                       fmaf(a.z, s, c.z), fmaf(a.w, s, c.w));
}
__device__ __forceinline__ void red4(float* p, float4 v) {
    asm volatile("red.global.add.v4.f32 [%0], {%1, %2, %3, %4};"
                 :: "l"(p), "f"(v.x), "f"(v.y), "f"(v.z), "f"(v.w)
                 : "memory");
}
__device__ __forceinline__ unsigned short bf_bits(__nv_bfloat16 h) {
    return *(unsigned short*)&h;
}
__device__ __forceinline__ void bf_split(float x, unsigned short& hi,
                                         unsigned short& lo) {
    const __nv_bfloat16 h = __float2bfloat16(x);
    const __nv_bfloat16 l = __float2bfloat16(x - __bfloat162float(h));
    hi = bf_bits(h);
    lo = bf_bits(l);
}

// mma.sync m16n8k16 bf16, fp32 accum
__device__ __forceinline__ void mma_bf16(float c[4], const uint4& a,
                                         uint32_t b0, uint32_t b1) {
    asm volatile(
        "mma.sync.aligned.m16n8k16.row.col.f32.bf16.bf16.f32 "
        "{%0,%1,%2,%3}, {%4,%5,%6,%7}, {%8,%9}, {%0,%1,%2,%3};"
        : "+f"(c[0]), "+f"(c[1]), "+f"(c[2]), "+f"(c[3])
        : "r"(a.x), "r"(a.y), "r"(a.z), "r"(a.w), "r"(b0), "r"(b1));
}

// cp.async + mbarrier helpers (sm_80/sm_90 core PTX)
__device__ __forceinline__ void cp16(void* dst_smem, const void* src) {
    uint32_t d = (uint32_t)__cvta_generic_to_shared(dst_smem);
    asm volatile("cp.async.cg.shared.global [%0], [%1], 16;"
                 :: "r"(d), "l"(src) : "memory");
}
#define MBAR_INIT(mb, n) \
    asm volatile("mbarrier.init.shared.b64 [%0], %1;" \
                 :: "r"(mb), "r"((uint32_t)(n)) : "memory")
#define MBAR_ARRIVE(mb) \
    asm volatile("mbarrier.arrive.shared.b64 _, [%0];" :: "r"(mb) : "memory")
#define CP_MBAR_ARRIVE(mb) \
    asm volatile("cp.async.mbarrier.arrive.noinc.shared.b64 [%0];" \
                 :: "r"(mb) : "memory")
#define MBAR_TRYWAIT(mb, par) do { \
    asm volatile( \
        "{\n\t.reg .pred P1;\n\t" \
        "WL_%=:\n\t" \
        "mbarrier.try_wait.parity.shared.b64 P1, [%0], %1;\n\t" \
        "@P1 bra.uni WD_%=;\n\t" \
        "bra.uni WL_%=;\n\t" \
        "WD_%=:\n\t}" \
        :: "r"(mb), "r"((uint32_t)(par)) : "memory"); \
} while (0)

// ---------------- K1: node pre-mix ------------------------------------------
__global__ __launch_bounds__(320) void k_node_pre(
    const float* __restrict__ nf, const float* __restrict__ Ws,
    const float* __restrict__ bs, const float* __restrict__ Wv)
{
    __shared__ float sv[8][320];
    const int n0 = blockIdx.x * 8;
    const int tid = threadIdx.x;

    for (int idx = tid; idx < 8 * 320; idx += 320) {
        sv[idx / 320][idx % 320] = nf[(n0 + idx / 320) * 320 + idx % 320];
    }
    __syncthreads();

    if (tid < 128) {
        const int j = tid;
        float acc[8];
#pragma unroll
        for (int i = 0; i < 8; i++) acc[i] = 0.0f;
        for (int u = 0; u < 128; u++) {
            const float w = Ws[u * 128 + j];
#pragma unroll
            for (int i = 0; i < 8; i++) acc[i] = fmaf(sv[i][u], w, acc[i]);
        }
        const float b = bs[j];
#pragma unroll
        for (int i = 0; i < 8; i++)
            g_xs[(n0 + i) * 128 + j] = fmaf(acc[i], INV_SQRT_NS, b);
    } else {
        const int t = tid - 128;
        const int c = t / 64, vp = t % 64;
        float acc[8];
#pragma unroll
        for (int i = 0; i < 8; i++) acc[i] = 0.0f;
        for (int u = 0; u < 64; u++) {
            const float w = Wv[u * 64 + vp];
#pragma unroll
            for (int i = 0; i < 8; i++)
                acc[i] = fmaf(sv[i][128 + 3 * u + c], w, acc[i]);
        }
#pragma unroll
        for (int i = 0; i < 8; i++)
            g_xv[(n0 + i) * 192 + c * 64 + vp] = acc[i] * INV_SQRT_NV;
    }
}

// ---------------- prep: W2 -> packed, PERMUTED B fragments -------------------
__global__ __launch_bounds__(256) void k_prep_b(const float* __restrict__ W2)
{
    const int idx = blockIdx.x * 256 + threadIdx.x;
    if (idx >= 6 * 8 * 8 * 32) return;
    const int lane = idx & 31;
    const int jj = (idx >> 5) & 7;       // n-frag within stage (0..7)
    const int s = (idx >> 8) & 7;        // k-step
    const int cs = idx >> 11;            // stage (0..5)

    const int gid = lane >> 2;
    const int tig = lane & 3;
    const int wcol = perm_col(cs, jj * 8 + gid);
    const int k0 = s * 16 + tig * 2;

    unsigned short h0, l0, h1, l1, h2, l2, h3, l3;
    bf_split(W2[k0 * 384 + wcol],       h0, l0);
    bf_split(W2[(k0 + 1) * 384 + wcol], h1, l1);
    bf_split(W2[(k0 + 8) * 384 + wcol], h2, l2);
    bf_split(W2[(k0 + 9) * 384 + wcol], h3, l3);

    uint4 p;
    p.x = (uint32_t)h0 | ((uint32_t)h1 << 16);   // b0_hi
    p.y = (uint32_t)h2 | ((uint32_t)h3 << 16);   // b1_hi
    p.z = (uint32_t)l0 | ((uint32_t)l1 << 16);   // b0_lo
    p.w = (uint32_t)l2 | ((uint32_t)l3 << 16);   // b1_lo
    g_Bpk[((cs * 8 + s) * 8 + jj) * 32 + lane] = p;
}

// ---------------- K2: edge MLP layer 1 -> h hi/lo bf16 -----------------------
__global__ __launch_bounds__(256) void k_edge_mlp1(
    const float* __restrict__ ea, const float* __restrict__ W1,
    const float* __restrict__ b1)
{
    __shared__ float W1s[16 * 128];
    __shared__ float b1s[128];
    __shared__ float eas[8][16];
    const int tid = threadIdx.x;
    const int e0 = blockIdx.x * 8;

    for (int idx = tid; idx < 2048; idx += 256) W1s[idx] = W1[idx];
    if (tid < 128) {
        b1s[tid] = b1[tid];
        eas[tid / 16][tid % 16] = ea[e0 * 16 + tid];
    }
    __syncthreads();

    const int i = tid >> 5;
    const int q = (tid & 31) * 4;
    float4 acc = *(const float4*)(b1s + q);
#pragma unroll
    for (int k = 0; k < 16; k++) {
        const float a = eas[i][k];
        const float4 w = *(const float4*)(W1s + k * 128 + q);
        acc = f4fmas(w, a, acc);
    }
    float v[4];
    v[0] = silu_f(acc.x); v[1] = silu_f(acc.y);
    v[2] = silu_f(acc.z); v[3] = silu_f(acc.w);

    unsigned short hb[4], lb[4];
#pragma unroll
    for (int j = 0; j < 4; j++) bf_split(v[j], hb[j], lb[j]);

    const size_t base = (size_t)(e0 + i) * 128 + q;
    uint2 ph, pl;
    ph.x = (uint32_t)hb[0] | ((uint32_t)hb[1] << 16);
    ph.y = (uint32_t)hb[2] | ((uint32_t)hb[3] << 16);
    pl.x = (uint32_t)lb[0] | ((uint32_t)lb[1] << 16);
    pl.y = (uint32_t)lb[2] | ((uint32_t)lb[3] << 16);
    *(uint2*)(g_hhi + base) = ph;
    *(uint2*)(g_hlo + base) = pl;
}

// ---------------- K3: FUSED tensor GEMM + message scatter (mbar pipeline) ----
#define SA_STRIDE 136
#define SMEM_A_IMG (128 * SA_STRIDE * 2)            // 34816 per image
#define SMEM_B_BYTES 32768
#define SMEM_WS_OFF (2 * SMEM_A_IMG)                // 69632
#define WS_STRIDE 68
#define SMEM_BIAS_OFF (SMEM_WS_OFF + 128 * WS_STRIDE * 4)   // 104448
#define SMEM_EIDX_OFF (SMEM_BIAS_OFF + 1536)        // 105984
#define SMEM_R_OFF    (SMEM_EIDX_OFF + 1024)        // 107008
#define SMEM_MB_OFF   (SMEM_R_OFF + 2048)           // 109056
#define SMEM_MMA_BYTES (SMEM_MB_OFF + 64)           // 109120
__global__ __launch_bounds__(256, 2) void k_mlp2_fused(
    const float* __restrict__ b2,
    const int* __restrict__ eidx, const float* __restrict__ rsh)
{
    extern __shared__ unsigned char smem[];
    __nv_bfloat16* sAh = (__nv_bfloat16*)smem;
    __nv_bfloat16* sAl = (__nv_bfloat16*)(smem + SMEM_A_IMG);
    float* ws = (float*)(smem + SMEM_WS_OFF);
    float* sbias = (float*)(smem + SMEM_BIAS_OFF);
    int* sDst = (int*)(smem + SMEM_EIDX_OFF);
    int* sSrc = sDst + 128;
    float4* sR4 = (float4*)(smem + SMEM_R_OFF);
    const uint32_t mbF =
        (uint32_t)__cvta_generic_to_shared(smem + SMEM_MB_OFF);
    const uint32_t mbE = mbF + 16;

    const int tid = threadIdx.x;
    const int warp = tid >> 5;
    const int lane = tid & 31;
    const int tile = blockIdx.x;
    const int gid = lane >> 2;
    const int tig = lane & 3;
    const int row0 = warp * 16 + gid;

    // ---- stage A once; load bias (permuted), edge meta; init mbarriers ----
    {
        const uint2* ghh = (const uint2*)(g_hhi + (size_t)tile * 16384);
        const uint2* ghl = (const uint2*)(g_hlo + (size_t)tile * 16384);
        for (int i = tid; i < 4096; i += 256) {
            const int r = i >> 5, q = (i & 31) * 4;
            *(uint2*)&sAh[r * SA_STRIDE + q] = ghh[i];
            *(uint2*)&sAl[r * SA_STRIDE + q] = ghl[i];
        }
    }
    for (int i = tid; i < 384; i += 256)
        sbias[i] = b2[perm_col(i / 64, i % 64)];
    if (tid < 128) {
        sDst[tid] = eidx[tile * 128 + tid];
        sSrc[tid] = eidx[NEDGES + tile * 128 + tid];
        sR4[tid] = *(const float4*)(rsh + 4 * (tile * 128 + tid));
    }
    if (tid == 0) {
        MBAR_INIT(mbF + 0, 256);
        MBAR_INIT(mbF + 8, 256);
        MBAR_INIT(mbE + 0, 256);
        MBAR_INIT(mbE + 8, 256);
    }
    __syncthreads();

    uint4 ah[8], al[8];
#pragma unroll
    for (int s = 0; s < 8; s++) {
        const int kb = s * 16 + tig * 2;
        ah[s].x = *(const uint32_t*)&sAh[row0 * SA_STRIDE + kb];
        ah[s].y = *(const uint32_t*)&sAh[(row0 + 8) * SA_STRIDE + kb];
        ah[s].z = *(const uint32_t*)&sAh[row0 * SA_STRIDE + kb + 8];
        ah[s].w = *(const uint32_t*)&sAh[(row0 + 8) * SA_STRIDE + kb + 8];
        al[s].x = *(const uint32_t*)&sAl[row0 * SA_STRIDE + kb];
        al[s].y = *(const uint32_t*)&sAl[(row0 + 8) * SA_STRIDE + kb];
        al[s].z = *(const uint32_t*)&sAl[row0 * SA_STRIDE + kb + 8];
        al[s].w = *(const uint32_t*)&sAl[(row0 + 8) * SA_STRIDE + kb + 8];
    }
    __syncthreads();     // A region released -> reused as B double buffer

    // prefetch stage 0 into buf0
    {
        const uint4* srcp = g_Bpk;
        uint4* dstp = (uint4*)smem;
#pragma unroll
        for (int i = 0; i < 8; i++)
            cp16(&dstp[tid + i * 256], &srcp[tid + i * 256]);
        CP_MBAR_ARRIVE(mbF + 0);
    }

    const int half16 = lane >> 4;        // edge of pair
    const int sub = lane & 15;
    const int typ = sub >> 3;            // 0: ss/vv, 1: sv/vs
    const int l4 = (sub & 7) * 4;        // col group within 32

    for (int cs = 0; cs < 6; cs++) {
        if (cs < 5) {
            const int b = (cs + 1) & 1;
            if (cs >= 1) MBAR_TRYWAIT(mbE + b * 8, ((cs - 1) >> 1) & 1);
            const uint4* srcp = g_Bpk + (cs + 1) * 2048;
            uint4* dstp = (uint4*)(smem + b * SMEM_B_BYTES);
#pragma unroll
            for (int i = 0; i < 8; i++)
                cp16(&dstp[tid + i * 256], &srcp[tid + i * 256]);
            CP_MBAR_ARRIVE(mbF + b * 8);
        }
        const int bc = cs & 1;
        MBAR_TRYWAIT(mbF + bc * 8, (cs >> 1) & 1);
        const uint4* bb = (const uint4*)(smem + bc * SMEM_B_BYTES);

        float c[8][4];
#pragma unroll
        for (int j = 0; j < 8; j++)
#pragma unroll
            for (int q = 0; q < 4; q++) c[j][q] = 0.0f;

#pragma unroll
        for (int s = 0; s < 8; s++) {
#pragma unroll
            for (int j = 0; j < 8; j++) {
                const uint4 b = bb[(s * 8 + j) * 32 + lane];
                mma_bf16(c[j], ah[s], b.x, b.y);
                mma_bf16(c[j], ah[s], b.z, b.w);
                mma_bf16(c[j], al[s], b.x, b.y);
            }
        }
        MBAR_ARRIVE(mbE + bc * 8);   // done reading this B buffer

        // ---- stage w to warp-local ws rows (bias added) ----
        const int cbase = cs * 64;
#pragma unroll
        for (int j = 0; j < 8; j++) {
            const int cl = j * 8 + tig * 2;
            const float bx = sbias[cbase + cl], by = sbias[cbase + cl + 1];
            *(float2*)&ws[row0 * WS_STRIDE + cl] =
                make_float2(c[j][0] + bx, c[j][1] + by);
            *(float2*)&ws[(row0 + 8) * WS_STRIDE + cl] =
                make_float2(c[j][2] + bx, c[j][3] + by);
        }
        __syncwarp();

        // ---- scatter: 2 edges per iter, 16 lanes each (typ splits cols) ----
#pragma unroll
        for (int it = 0; it < 8; it++) {
            const int t = warp * 16 + it * 2 + half16;
            const int dst = sDst[t];
            const int src = sSrc[t];
            const float4 r = sR4[t];
            const float4 w = *(const float4*)&ws[t * WS_STRIDE + typ * 32 + l4];
            float* as_ = g_accs + dst * 192;
            float* av = g_accv + dst * 576;

            if (cs < 4) {
                const int scol = cs * 32 + l4;
                const float4 sj = *(const float4*)(g_xs + src * 128 + scol);
                if (typ == 0) {
                    red4(as_ + scol, f4scale(f4mul(w, sj), r.x));
                } else {
                    const float4 base = f4mul(w, sj);
                    red4(av + scol,       f4scale(base, r.y));
                    red4(av + 192 + scol, f4scale(base, r.z));
                    red4(av + 384 + scol, f4scale(base, r.w));
                }
            } else {
                const int u = (cs - 4) * 32 + l4;
                const float* xv = g_xv + src * 192;
                const float4 v0 = *(const float4*)(xv + u);
                const float4 v1 = *(const float4*)(xv + 64 + u);
                const float4 v2 = *(const float4*)(xv + 128 + u);
                if (typ == 0) {
                    float4 vd = f4scale(v0, r.y);
                    vd = f4fmas(v1, r.z, vd);
                    vd = f4fmas(v2, r.w, vd);
                    red4(as_ + 128 + u, f4scale(f4mul(w, vd), INV_SQRT3));
                } else {
                    const float4 wr = f4scale(w, r.x);
                    red4(av + 128 + u, f4mul(wr, v0));
                    red4(av + 320 + u, f4mul(wr, v1));
                    red4(av + 512 + u, f4mul(wr, v2));
                }
            }
        }
    }
}

// ---------------- K5: gating + node post-mix + residual (f4 inner loops) -----
__global__ __launch_bounds__(320) void k_node_post(
    const float* __restrict__ Wps, const float* __restrict__ Wpv,
    float* __restrict__ out)
{
    __shared__ float gs[8][192];
    __shared__ float gv[8][3][192];
    const int n0 = blockIdx.x * 8;
    const int tid = threadIdx.x;

    for (int idx = tid; idx < 8 * 192; idx += 320) {
        const int i = idx / 192, u = idx % 192;
        const float a = g_accs[(n0 + i) * 192 + u];
        gs[i][u] = silu_f(a);
        const float v0 = g_accv[(n0 + i) * 576 + u];
        const float v1 = g_accv[(n0 + i) * 576 + 192 + u];
        const float v2 = g_accv[(n0 + i) * 576 + 384 + u];
        const float nrm = sqrtf(fmaf(v0, v0, fmaf(v1, v1, fmaf(v2, v2, 1e-12f))));
        const float sg = 1.0f / (1.0f + __expf(-nrm));
        gv[i][0][u] = v0 * sg;
        gv[i][1][u] = v1 * sg;
        gv[i][2][u] = v2 * sg;
    }
    __syncthreads();

    if (tid < 128) {
        const int j = tid;
        float acc[8];
#pragma unroll
        for (int i = 0; i < 8; i++) acc[i] = 0.0f;
        for (int u = 0; u < 192; u += 4) {
            float4 w;
            w.x = Wps[u * 128 + j];
            w.y = Wps[(u + 1) * 128 + j];
            w.z = Wps[(u + 2) * 128 + j];
            w.w = Wps[(u + 3) * 128 + j];
#pragma unroll
            for (int i = 0; i < 8; i++) {
                const float4 g = *(const float4*)&gs[i][u];
                acc[i] = fmaf(g.x, w.x, acc[i]);
                acc[i] = fmaf(g.y, w.y, acc[i]);
                acc[i] = fmaf(g.z, w.z, acc[i]);
                acc[i] = fmaf(g.w, w.w, acc[i]);
            }
        }
#pragma unroll
        for (int i = 0; i < 8; i++)
            out[(n0 + i) * 320 + j] =
                g_xs[(n0 + i) * 128 + j] + acc[i] * INV_SQRT_TPC;
    } else {
        const int t = tid - 128;
        const int c = t / 64, vp = t % 64;
        float acc[8];
#pragma unroll
        for (int i = 0; i < 8; i++) acc[i] = 0.0f;
        for (int u = 0; u < 192; u += 4) {
            float4 w;
            w.x = Wpv[u * 64 + vp];
            w.y = Wpv[(u + 1) * 64 + vp];
            w.z = Wpv[(u + 2) * 64 + vp];
            w.w = Wpv[(u + 3) * 64 + vp];
#pragma unroll
            for (int i = 0; i < 8; i++) {
                const float4 g = *(const float4*)&gv[i][c][u];
                acc[i] = fmaf(g.x, w.x, acc[i]);
                acc[i] = fmaf(g.y, w.y, acc[i]);
                acc[i] = fmaf(g.z, w.z, acc[i]);
                acc[i] = fmaf(g.w, w.w, acc[i]);
            }
        }
#pragma unroll
        for (int i = 0; i < 8; i++)
            out[(n0 + i) * 320 + 128 + vp * 3 + c] =
                g_xv[(n0 + i) * 192 + c * 64 + vp] + acc[i] * INV_SQRT_TPC;
    }
}

// ---------------- launcher ---------------------------------------------------
extern "C" void kernel_launch(void* const* d_in, const int* in_sizes, int n_in,
                              void* d_out, int out_size)
{
    (void)in_sizes; (void)n_in; (void)out_size;
    const float* nf   = (const float*)d_in[0];
    const float* ea   = (const float*)d_in[1];
    const float* rsh  = (const float*)d_in[2];
    const int*   eidx = (const int*)d_in[3];
    const float* Wps  = (const float*)d_in[4];
    const float* bps  = (const float*)d_in[5];
    const float* Wpv  = (const float*)d_in[6];
    const float* W1   = (const float*)d_in[7];
    const float* b1   = (const float*)d_in[8];
    const float* W2   = (const float*)d_in[9];
    const float* b2   = (const float*)d_in[10];
    const float* Wposts = (const float*)d_in[11];
    const float* Wpostv = (const float*)d_in[12];
    float* out = (float*)d_out;

    cudaFuncSetAttribute(k_mlp2_fused,
                         cudaFuncAttributeMaxDynamicSharedMemorySize,
                         SMEM_MMA_BYTES);

    void* accs_ptr = nullptr;
    void* accv_ptr = nullptr;
    cudaGetSymbolAddress(&accs_ptr, g_accs);
    cudaGetSymbolAddress(&accv_ptr, g_accv);
    cudaMemsetAsync(accs_ptr, 0, sizeof(float) * NNODES * TPCC);
    cudaMemsetAsync(accv_ptr, 0, sizeof(float) * NNODES * 3 * TPCC);

    k_node_pre<<<NNODES / 8, 320>>>(nf, Wps, bps, Wpv);
    k_prep_b<<<48, 256>>>(W2);
    k_edge_mlp1<<<NEDGES / 8, 256>>>(ea, W1, b1);
    k_mlp2_fused<<<NTILES, 256, SMEM_MMA_BYTES>>>(b2, eidx, rsh);
    k_node_post<<<NNODES / 8, 320>>>(Wposts, Wpostv, out);
}